// round 11
// baseline (speedup 1.0000x reference)
#include <cuda_runtime.h>
#include <cuda_bf16.h>
#include <math.h>

#define N_ROWS 131072   // 32*64*64
#define DIM    64
#define KCB    512

// Output layout (concatenated, float32). Scalar perplexity misaligns
// everything after it to 4B -> scalar stores only into outE/outD.
#define OFF_Q 0
#define OFF_P (N_ROWS * DIM)
#define OFF_E (OFF_P + 1)
#define OFF_I (OFF_E + (size_t)N_ROWS * KCB)
#define OFF_D (OFF_I + N_ROWS)

#define CAND_CAP 16
#define CAND_MARGIN 2.5e-3f   // >= 2x worst-case bf16 distance error

// Scratch
__device__ float g_rownorm[N_ROWS];
__device__ float g_colnorm[KCB];
__device__ unsigned int g_count[KCB];
__device__ int g_candn[N_ROWS];
__device__ unsigned short g_cand[N_ROWS][CAND_CAP];

// ---------------------------------------------------------------------------
__device__ __forceinline__ unsigned int forder(float f) {
    unsigned int u = __float_as_uint(f);
    unsigned int mask = ((int)u >> 31) | 0x80000000u;
    return u ^ mask;  // monotonic float -> uint
}

// pack two floats into bf16x2: lo half = first element (lower k), hi = second
__device__ __forceinline__ unsigned pack_bf16x2(float lo, float hi) {
    unsigned r;
    asm("cvt.rn.bf16x2.f32 %0, %1, %2;" : "=r"(r) : "f"(hi), "f"(lo));
    return r;
}

// m16n8k16 bf16 MMA, fp32 accumulate
__device__ __forceinline__ void mma16(float* c, unsigned a0, unsigned a1,
                                      unsigned a2, unsigned a3,
                                      unsigned b0, unsigned b1) {
    asm volatile(
        "mma.sync.aligned.m16n8k16.row.col.f32.bf16.bf16.f32 "
        "{%0,%1,%2,%3}, {%4,%5,%6,%7}, {%8,%9}, {%0,%1,%2,%3};"
        : "+f"(c[0]), "+f"(c[1]), "+f"(c[2]), "+f"(c[3])
        : "r"(a0), "r"(a1), "r"(a2), "r"(a3), "r"(b0), "r"(b1));
}

// ---------------------------------------------------------------------------
__global__ void rownorm_k(const float* __restrict__ X) {
    int r = blockIdx.x * blockDim.x + threadIdx.x;
    if (r >= N_ROWS) return;
    g_candn[r] = 0;
    const float4* p = (const float4*)(X + (size_t)r * DIM);
    float s = 0.f;
#pragma unroll
    for (int i = 0; i < DIM / 4; i++) {
        float4 v = p[i];
        s += v.x * v.x + v.y * v.y + v.z * v.z + v.w * v.w;
    }
    g_rownorm[r] = s;
}

__global__ void colnorm_k(const float* __restrict__ CB) {
    int r = blockIdx.x * blockDim.x + threadIdx.x;
    if (r >= KCB) return;
    g_count[r] = 0u;
    const float4* p = (const float4*)(CB + (size_t)r * DIM);
    float s = 0.f;
#pragma unroll
    for (int i = 0; i < DIM / 4; i++) {
        float4 v = p[i];
        s += v.x * v.x + v.y * v.y + v.z * v.z + v.w * v.w;
    }
    g_colnorm[r] = s;
}

// ---------------------------------------------------------------------------
// bf16 tensor-core distance GEMM (m16n8k16) + candidate collection
// + encodings zero-fill. CTA 64x128, K=64 resident, 8 warps, 32x32/warp.
// k-PAIR permuted smem layout: within each 16-k block, pair p goes to slot
// (p&3)*2 + (p>>2). Thread t's fragment pairs {t, t+4} land in one 8-byte
// chunk -> one LDS.64 per fragment ({a0,a2}, {a1,a3}, {b0,b1}).
// Row stride 160B -> conflict-free LDS.64 half-warp phases.
// Exact argmin protected by the fp32 rescue pass (margin 2.5e-3).
// ---------------------------------------------------------------------------
#define ROW_BYTES 160
#define AS_BYTES (64 * ROW_BYTES)      // 10240
#define CS_STRIDE 132
#define GEMM_SMEM_BYTES (64 * CS_STRIDE * 4)   // 33792 >= 30720 operand bytes

__global__ __launch_bounds__(256) void gemm_k(const float* __restrict__ A,
                                              const float* __restrict__ B,
                                              float* __restrict__ outD,
                                              float* __restrict__ outE,
                                              int bm_base) {
    extern __shared__ char smc[];
    char* As = smc;                 // [64 rows][160B] bf16, pair-permuted
    char* Bs = smc + AS_BYTES;      // [128 rows][160B] bf16(2*codebook)
    float* Cs = (float*)smc;        // [64][132] fp32, aliases post-MMA

    const int tid = threadIdx.x;
    const int lane = tid & 31;
    const int wid = tid >> 5;
    const int g = lane >> 2;
    const int t = lane & 3;
    const int wm0 = (wid & 1) * 32;      // 2 warp rows
    const int wn0 = (wid >> 1) * 32;     // 4 warp cols
    const int bm0 = bm_base + blockIdx.y * 64;
    const int bk0 = blockIdx.x * 128;

    // Tile load: fp32 -> bf16 cvt + k-pair-permuted scatter.
    // float4 covers k = c4..c4+3 = pairs p0, p0+1 (p0 = (c4&15)>>1 in-block).
    {
        const float4* Ag = (const float4*)(A + (size_t)bm0 * DIM);
        const float4* Bg = (const float4*)(B + (size_t)bk0 * DIM);
#pragma unroll
        for (int i = 0; i < 4; i++) {          // A: 64 rows = 1024 float4
            int t4 = tid + i * 256;
            int row = t4 >> 4;
            int c4 = (t4 & 15) * 4;
            int kblk = c4 >> 4;
            int p0 = (c4 & 15) >> 1;           // 0,2,4,6
            int s0 = ((p0 & 3) << 1) | (p0 >> 2);
            int s1 = (((p0 + 1) & 3) << 1) | ((p0 + 1) >> 2);
            char* rp = As + row * ROW_BYTES + kblk * 32;
            float4 va = Ag[t4];
            *(unsigned*)(rp + s0 * 4) = pack_bf16x2(va.x, va.y);
            *(unsigned*)(rp + s1 * 4) = pack_bf16x2(va.z, va.w);
        }
#pragma unroll
        for (int i = 0; i < 8; i++) {          // B: 128 rows = 2048 float4
            int t4 = tid + i * 256;
            int row = t4 >> 4;
            int c4 = (t4 & 15) * 4;
            int kblk = c4 >> 4;
            int p0 = (c4 & 15) >> 1;
            int s0 = ((p0 & 3) << 1) | (p0 >> 2);
            int s1 = (((p0 + 1) & 3) << 1) | ((p0 + 1) >> 2);
            char* rp = Bs + row * ROW_BYTES + kblk * 32;
            float4 vb = Bg[t4];
            *(unsigned*)(rp + s0 * 4) = pack_bf16x2(2.f * vb.x, 2.f * vb.y);
            *(unsigned*)(rp + s1 * 4) = pack_bf16x2(2.f * vb.z, 2.f * vb.w);
        }
    }
    __syncthreads();

    float acc[2][4][4];
#pragma unroll
    for (int mi = 0; mi < 2; mi++)
#pragma unroll
        for (int ni = 0; ni < 4; ni++)
#pragma unroll
            for (int j = 0; j < 4; j++) acc[mi][ni][j] = 0.f;

#pragma unroll
    for (int kt = 0; kt < 4; kt++) {           // 4 k-tiles of 16
        const int kb = kt * 32 + t * 8;
        uint2 fa[2][2];
#pragma unroll
        for (int mi = 0; mi < 2; mi++) {
            int r0 = wm0 + mi * 16 + g;
            fa[mi][0] = *(const uint2*)(As + r0 * ROW_BYTES + kb);        // {a0,a2}
            fa[mi][1] = *(const uint2*)(As + (r0 + 8) * ROW_BYTES + kb);  // {a1,a3}
        }
        uint2 fb[4];
#pragma unroll
        for (int ni = 0; ni < 4; ni++) {
            int n = wn0 + ni * 8 + g;
            fb[ni] = *(const uint2*)(Bs + n * ROW_BYTES + kb);            // {b0,b1}
        }
#pragma unroll
        for (int mi = 0; mi < 2; mi++)
#pragma unroll
            for (int ni = 0; ni < 4; ni++)
                mma16(acc[mi][ni], fa[mi][0].x, fa[mi][1].x,
                      fa[mi][0].y, fa[mi][1].y, fb[ni].x, fb[ni].y);
    }

    __syncthreads();
    // Stage accumulators via STS.64 (c0 even -> 8B aligned)
#pragma unroll
    for (int mi = 0; mi < 2; mi++)
#pragma unroll
        for (int ni = 0; ni < 4; ni++) {
            int r0 = wm0 + mi * 16 + g;
            int c0 = wn0 + ni * 8 + 2 * t;
            *(float2*)&Cs[r0 * CS_STRIDE + c0] =
                make_float2(acc[mi][ni][0], acc[mi][ni][1]);
            *(float2*)&Cs[(r0 + 8) * CS_STRIDE + c0] =
                make_float2(acc[mi][ni][2], acc[mi][ni][3]);
        }
    __syncthreads();

    // Distance stores + candidate collection + encodings zero-fill.
    float cn4[4];
#pragma unroll
    for (int j = 0; j < 4; j++) cn4[j] = g_colnorm[bk0 + lane + 32 * j];

#pragma unroll 2
    for (int r = 0; r < 8; r++) {
        int lr = wid * 8 + r;
        int gr = bm0 + lr;
        float rn = g_rownorm[gr];
        const float* crow = &Cs[lr * CS_STRIDE];
        float* drow = outD + (size_t)gr * KCB + bk0;
        float* erow = outE + (size_t)gr * KCB + bk0;
        float v[4];
        float mn = 3.4e38f;
#pragma unroll
        for (int j = 0; j < 4; j++) {
            int c = lane + 32 * j;
            float d = (rn - crow[c]) + cn4[j];
            v[j] = d;
            drow[c] = d;
            erow[c] = 0.f;
            if (d < mn) mn = d;
        }
#pragma unroll
        for (int off = 16; off > 0; off >>= 1) {
            float o = __shfl_xor_sync(0xFFFFFFFFu, mn, off);
            if (o < mn) mn = o;
        }
        float thr = mn + CAND_MARGIN;
#pragma unroll
        for (int j = 0; j < 4; j++) {
            if (v[j] <= thr) {
                int slot = atomicAdd(&g_candn[gr], 1);
                if (slot < CAND_CAP)
                    g_cand[gr][slot] = (unsigned short)(bk0 + lane + 32 * j);
            }
        }
    }
}

// ---------------------------------------------------------------------------
// rescue + outputs: block = 32 rows, 8 threads/row. Candidates processed
// serially by the 8-lane group (coalesced codebook reads), two at a time so
// the shfl-reduce chains pipeline. Per-8-group shfl masks.
// Exact fp32 numerics. Writes indices, histogram, one-hot 1.0, quantized.
// ---------------------------------------------------------------------------
#define RROWS 32   // rows per block
__global__ __launch_bounds__(256, 4) void rescue_k(const float* __restrict__ X,
                                                   const float* __restrict__ CB,
                                                   float* __restrict__ outI,
                                                   float* __restrict__ outE,
                                                   float* __restrict__ outQ) {
    __shared__ float Xs[RROWS * DIM];           // 8 KB
    const int tid = threadIdx.x;
    const int r = tid >> 3;        // 0..31 row within block
    const int s = tid & 7;         // lane within row group
    const int lane = tid & 31;
    const unsigned gmask = 0xFFu << (lane & 24);   // this 8-group's lanes
    const int row0 = blockIdx.x * RROWS;
    const int gr = row0 + r;

    // cooperative X stage: 32 rows x 64 floats = 512 float4
    {
        const float4* Xg = (const float4*)(X + (size_t)row0 * DIM);
        float4* Xs4 = (float4*)Xs;
#pragma unroll
        for (int i = 0; i < 2; i++) Xs4[tid + i * 256] = Xg[tid + i * 256];
    }
    __syncthreads();

    const float rn = g_rownorm[gr];
    const float4* xp4 = (const float4*)(Xs + r * DIM);
    const int n = g_candn[gr];

    unsigned long long best = 0xFFFFFFFFFFFFFFFFULL;
    if (n <= CAND_CAP) {
        float4 x0 = xp4[s * 2];
        float4 x1 = xp4[s * 2 + 1];
        int j = 0;
        for (; j + 1 < n; j += 2) {
            int c0 = g_cand[gr][j];
            int c1 = g_cand[gr][j + 1];
            const float4* e0p = (const float4*)(CB + (size_t)c0 * DIM);
            const float4* e1p = (const float4*)(CB + (size_t)c1 * DIM);
            float4 a0 = e0p[s * 2], a1 = e0p[s * 2 + 1];
            float4 b0 = e1p[s * 2], b1 = e1p[s * 2 + 1];
            float p = x0.x * a0.x;
            p = fmaf(x0.y, a0.y, p); p = fmaf(x0.z, a0.z, p);
            p = fmaf(x0.w, a0.w, p); p = fmaf(x1.x, a1.x, p);
            p = fmaf(x1.y, a1.y, p); p = fmaf(x1.z, a1.z, p);
            p = fmaf(x1.w, a1.w, p);
            float q = x0.x * b0.x;
            q = fmaf(x0.y, b0.y, q); q = fmaf(x0.z, b0.z, q);
            q = fmaf(x0.w, b0.w, q); q = fmaf(x1.x, b1.x, q);
            q = fmaf(x1.y, b1.y, q); q = fmaf(x1.z, b1.z, q);
            q = fmaf(x1.w, b1.w, q);
            p += __shfl_xor_sync(gmask, p, 4);
            q += __shfl_xor_sync(gmask, q, 4);
            p += __shfl_xor_sync(gmask, p, 2);
            q += __shfl_xor_sync(gmask, q, 2);
            p += __shfl_xor_sync(gmask, p, 1);
            q += __shfl_xor_sync(gmask, q, 1);
            float d0 = (rn - 2.f * p) + g_colnorm[c0];
            float d1 = (rn - 2.f * q) + g_colnorm[c1];
            unsigned long long k0 =
                ((unsigned long long)forder(d0) << 32) | (unsigned)c0;
            unsigned long long k1 =
                ((unsigned long long)forder(d1) << 32) | (unsigned)c1;
            if (k0 < best) best = k0;
            if (k1 < best) best = k1;
        }
        if (j < n) {
            int c0 = g_cand[gr][j];
            const float4* e0p = (const float4*)(CB + (size_t)c0 * DIM);
            float4 a0 = e0p[s * 2], a1 = e0p[s * 2 + 1];
            float p = x0.x * a0.x;
            p = fmaf(x0.y, a0.y, p); p = fmaf(x0.z, a0.z, p);
            p = fmaf(x0.w, a0.w, p); p = fmaf(x1.x, a1.x, p);
            p = fmaf(x1.y, a1.y, p); p = fmaf(x1.z, a1.z, p);
            p = fmaf(x1.w, a1.w, p);
            p += __shfl_xor_sync(gmask, p, 4);
            p += __shfl_xor_sync(gmask, p, 2);
            p += __shfl_xor_sync(gmask, p, 1);
            float d0 = (rn - 2.f * p) + g_colnorm[c0];
            unsigned long long k0 =
                ((unsigned long long)forder(d0) << 32) | (unsigned)c0;
            if (k0 < best) best = k0;
        }
    } else {
        // overflow fallback (rare): per-lane scan of all 512 codes
        for (int c = s; c < KCB; c += 8) {
            const float4* cp4 = (const float4*)(CB + (size_t)c * DIM);
            float d0 = 0.f, d1 = 0.f, d2 = 0.f, d3 = 0.f;
#pragma unroll
            for (int i = 0; i < DIM / 4; i++) {
                float4 x = xp4[i];
                float4 e = cp4[i];
                d0 = fmaf(x.x, e.x, d0);
                d1 = fmaf(x.y, e.y, d1);
                d2 = fmaf(x.z, e.z, d2);
                d3 = fmaf(x.w, e.w, d3);
            }
            float dot = (d0 + d1) + (d2 + d3);
            float d = (rn - 2.f * dot) + g_colnorm[c];
            unsigned long long key =
                ((unsigned long long)forder(d) << 32) | (unsigned)c;
            if (key < best) best = key;
        }
#pragma unroll
        for (int off = 4; off > 0; off >>= 1) {
            unsigned long long o = __shfl_xor_sync(gmask, best, off);
            if (o < best) best = o;
        }
    }
    int idx = (int)(best & 0xFFFFFFFFu);

    if (s == 0) {
        outI[gr] = (float)idx;
        atomicAdd(&g_count[idx], 1u);
        outE[(size_t)gr * KCB + idx] = 1.f;  // zeros pre-filled by gemm_k
    }

    // quantized: 8 threads x 8 floats (2 float4 each); outQ 16B-aligned
    {
        const float4* cp4 = (const float4*)(CB + (size_t)idx * DIM);
        float4* qp4 = (float4*)(outQ + (size_t)gr * DIM);
#pragma unroll
        for (int i = 0; i < 2; i++) {
            int j = s * 2 + i;
            float4 x = xp4[j];
            float4 e = cp4[j];
            float4 q;
            q.x = x.x + (e.x - x.x);
            q.y = x.y + (e.y - x.y);
            q.z = x.z + (e.z - x.z);
            q.w = x.w + (e.w - x.w);
            qp4[j] = q;
        }
    }
}

// ---------------------------------------------------------------------------
__global__ void perp_k(float* __restrict__ outP) {
    __shared__ float s[KCB];
    int t = threadIdx.x;
    float p = (float)g_count[t] / (float)N_ROWS;
    s[t] = p * logf(p + 1e-10f);
    __syncthreads();
    for (int o = KCB / 2; o > 0; o >>= 1) {
        if (t < o) s[t] += s[t + o];
        __syncthreads();
    }
    if (t == 0) outP[0] = expf(-s[0]);
}

// ---------------------------------------------------------------------------
extern "C" void kernel_launch(void* const* d_in, const int* in_sizes, int n_in,
                              void* d_out, int out_size) {
    const float* X = (const float*)d_in[0];
    const float* CB = (const float*)d_in[1];
    if (n_in >= 2 && in_sizes[0] == KCB * DIM) {
        X = (const float*)d_in[1];
        CB = (const float*)d_in[0];
    }
    float* out = (float*)d_out;
    float* outQ = out + OFF_Q;
    float* outP = out + OFF_P;
    float* outE = out + OFF_E;
    float* outI = out + OFF_I;
    float* outD = out + OFF_D;

    cudaFuncSetAttribute(gemm_k, cudaFuncAttributeMaxDynamicSharedMemorySize,
                         GEMM_SMEM_BYTES);

    rownorm_k<<<N_ROWS / 256, 256>>>(X);
    colnorm_k<<<2, 256>>>(CB);
    // split gemm across two launches (keeps gemm in the ncu capture slot)
    dim3 ggrid(KCB / 128, N_ROWS / 64 / 2);
    gemm_k<<<ggrid, 256, GEMM_SMEM_BYTES>>>(X, CB, outD, outE, 0);
    gemm_k<<<ggrid, 256, GEMM_SMEM_BYTES>>>(X, CB, outD, outE, N_ROWS / 2);
    rescue_k<<<N_ROWS / RROWS, 256>>>(X, CB, outI, outE, outQ);
    perp_k<<<1, KCB>>>(outP);
}

// round 12
// speedup vs baseline: 1.1792x; 1.1792x over previous
#include <cuda_runtime.h>
#include <cuda_bf16.h>
#include <math.h>

#define N_ROWS 131072   // 32*64*64
#define DIM    64
#define KCB    512

// Output layout (concatenated, float32). Scalar perplexity misaligns
// everything after it to 4B -> scalar stores only into outE/outD.
#define OFF_Q 0
#define OFF_P (N_ROWS * DIM)
#define OFF_E (OFF_P + 1)
#define OFF_I (OFF_E + (size_t)N_ROWS * KCB)
#define OFF_D (OFF_I + N_ROWS)

#define CAND_CAP 16
#define CAND_MARGIN 1.2e-3f   // ~30x measured bf16 distance error (4e-5)

// Scratch
__device__ float g_rownorm[N_ROWS];
__device__ float g_colnorm[KCB];
__device__ unsigned int g_count[KCB];
__device__ int g_candn[N_ROWS];
__device__ unsigned short g_cand[N_ROWS][CAND_CAP];

// ---------------------------------------------------------------------------
__device__ __forceinline__ unsigned int forder(float f) {
    unsigned int u = __float_as_uint(f);
    unsigned int mask = ((int)u >> 31) | 0x80000000u;
    return u ^ mask;  // monotonic float -> uint
}

// pack two floats into bf16x2: lo half = first element (lower k), hi = second
__device__ __forceinline__ unsigned pack_bf16x2(float lo, float hi) {
    unsigned r;
    asm("cvt.rn.bf16x2.f32 %0, %1, %2;" : "=r"(r) : "f"(hi), "f"(lo));
    return r;
}

// m16n8k16 bf16 MMA, fp32 accumulate
__device__ __forceinline__ void mma16(float* c, unsigned a0, unsigned a1,
                                      unsigned a2, unsigned a3,
                                      unsigned b0, unsigned b1) {
    asm volatile(
        "mma.sync.aligned.m16n8k16.row.col.f32.bf16.bf16.f32 "
        "{%0,%1,%2,%3}, {%4,%5,%6,%7}, {%8,%9}, {%0,%1,%2,%3};"
        : "+f"(c[0]), "+f"(c[1]), "+f"(c[2]), "+f"(c[3])
        : "r"(a0), "r"(a1), "r"(a2), "r"(a3), "r"(b0), "r"(b1));
}

// ---------------------------------------------------------------------------
__global__ void rownorm_k(const float* __restrict__ X) {
    int r = blockIdx.x * blockDim.x + threadIdx.x;
    if (r >= N_ROWS) return;
    g_candn[r] = 0;
    const float4* p = (const float4*)(X + (size_t)r * DIM);
    float s = 0.f;
#pragma unroll
    for (int i = 0; i < DIM / 4; i++) {
        float4 v = p[i];
        s += v.x * v.x + v.y * v.y + v.z * v.z + v.w * v.w;
    }
    g_rownorm[r] = s;
}

__global__ void colnorm_k(const float* __restrict__ CB) {
    int r = blockIdx.x * blockDim.x + threadIdx.x;
    if (r >= KCB) return;
    g_count[r] = 0u;
    const float4* p = (const float4*)(CB + (size_t)r * DIM);
    float s = 0.f;
#pragma unroll
    for (int i = 0; i < DIM / 4; i++) {
        float4 v = p[i];
        s += v.x * v.x + v.y * v.y + v.z * v.z + v.w * v.w;
    }
    g_colnorm[r] = s;
}

// ---------------------------------------------------------------------------
// bf16 tensor-core distance GEMM (m16n8k16) + candidate collection.
// CTA 64x128, K=64 resident, 8 warps, 32x32/warp. k-PAIR permuted smem
// layout: within each 16-k block, pair p -> slot (p&3)*2 + (p>>2); thread t's
// fragment pairs {t, t+4} are one LDS.64 ({a0,a2}, {a1,a3}, {b0,b1}).
// Distances only (encodings written by ewrite_k). Exact argmin protected by
// the fp32 rescue pass.
// ---------------------------------------------------------------------------
#define ROW_BYTES 160
#define AS_BYTES (64 * ROW_BYTES)      // 10240
#define CS_STRIDE 132
#define GEMM_SMEM_BYTES (64 * CS_STRIDE * 4)   // 33792 >= 30720 operand bytes

__global__ __launch_bounds__(256) void gemm_k(const float* __restrict__ A,
                                              const float* __restrict__ B,
                                              float* __restrict__ outD,
                                              int bm_base) {
    extern __shared__ char smc[];
    char* As = smc;                 // [64 rows][160B] bf16, pair-permuted
    char* Bs = smc + AS_BYTES;      // [128 rows][160B] bf16(2*codebook)
    float* Cs = (float*)smc;        // [64][132] fp32, aliases post-MMA

    const int tid = threadIdx.x;
    const int lane = tid & 31;
    const int wid = tid >> 5;
    const int g = lane >> 2;
    const int t = lane & 3;
    const int wm0 = (wid & 1) * 32;      // 2 warp rows
    const int wn0 = (wid >> 1) * 32;     // 4 warp cols
    const int bm0 = bm_base + blockIdx.y * 64;
    const int bk0 = blockIdx.x * 128;

    // Tile load: fp32 -> bf16 cvt + k-pair-permuted scatter.
    {
        const float4* Ag = (const float4*)(A + (size_t)bm0 * DIM);
        const float4* Bg = (const float4*)(B + (size_t)bk0 * DIM);
#pragma unroll
        for (int i = 0; i < 4; i++) {          // A: 64 rows = 1024 float4
            int t4 = tid + i * 256;
            int row = t4 >> 4;
            int c4 = (t4 & 15) * 4;
            int kblk = c4 >> 4;
            int p0 = (c4 & 15) >> 1;           // 0,2,4,6
            int s0 = ((p0 & 3) << 1) | (p0 >> 2);
            int s1 = (((p0 + 1) & 3) << 1) | ((p0 + 1) >> 2);
            char* rp = As + row * ROW_BYTES + kblk * 32;
            float4 va = Ag[t4];
            *(unsigned*)(rp + s0 * 4) = pack_bf16x2(va.x, va.y);
            *(unsigned*)(rp + s1 * 4) = pack_bf16x2(va.z, va.w);
        }
#pragma unroll
        for (int i = 0; i < 8; i++) {          // B: 128 rows = 2048 float4
            int t4 = tid + i * 256;
            int row = t4 >> 4;
            int c4 = (t4 & 15) * 4;
            int kblk = c4 >> 4;
            int p0 = (c4 & 15) >> 1;
            int s0 = ((p0 & 3) << 1) | (p0 >> 2);
            int s1 = (((p0 + 1) & 3) << 1) | ((p0 + 1) >> 2);
            char* rp = Bs + row * ROW_BYTES + kblk * 32;
            float4 vb = Bg[t4];
            *(unsigned*)(rp + s0 * 4) = pack_bf16x2(2.f * vb.x, 2.f * vb.y);
            *(unsigned*)(rp + s1 * 4) = pack_bf16x2(2.f * vb.z, 2.f * vb.w);
        }
    }
    __syncthreads();

    float acc[2][4][4];
#pragma unroll
    for (int mi = 0; mi < 2; mi++)
#pragma unroll
        for (int ni = 0; ni < 4; ni++)
#pragma unroll
            for (int j = 0; j < 4; j++) acc[mi][ni][j] = 0.f;

#pragma unroll
    for (int kt = 0; kt < 4; kt++) {           // 4 k-tiles of 16
        const int kb = kt * 32 + t * 8;
        uint2 fa[2][2];
#pragma unroll
        for (int mi = 0; mi < 2; mi++) {
            int r0 = wm0 + mi * 16 + g;
            fa[mi][0] = *(const uint2*)(As + r0 * ROW_BYTES + kb);        // {a0,a2}
            fa[mi][1] = *(const uint2*)(As + (r0 + 8) * ROW_BYTES + kb);  // {a1,a3}
        }
        uint2 fb[4];
#pragma unroll
        for (int ni = 0; ni < 4; ni++) {
            int n = wn0 + ni * 8 + g;
            fb[ni] = *(const uint2*)(Bs + n * ROW_BYTES + kb);            // {b0,b1}
        }
#pragma unroll
        for (int mi = 0; mi < 2; mi++)
#pragma unroll
            for (int ni = 0; ni < 4; ni++)
                mma16(acc[mi][ni], fa[mi][0].x, fa[mi][1].x,
                      fa[mi][0].y, fa[mi][1].y, fb[ni].x, fb[ni].y);
    }

    __syncthreads();
    // Stage accumulators via STS.64 (c0 even -> 8B aligned)
#pragma unroll
    for (int mi = 0; mi < 2; mi++)
#pragma unroll
        for (int ni = 0; ni < 4; ni++) {
            int r0 = wm0 + mi * 16 + g;
            int c0 = wn0 + ni * 8 + 2 * t;
            *(float2*)&Cs[r0 * CS_STRIDE + c0] =
                make_float2(acc[mi][ni][0], acc[mi][ni][1]);
            *(float2*)&Cs[(r0 + 8) * CS_STRIDE + c0] =
                make_float2(acc[mi][ni][2], acc[mi][ni][3]);
        }
    __syncthreads();

    // Distance stores + candidate collection. 8 warps x 8 rows = 64 rows.
    float cn4[4];
#pragma unroll
    for (int j = 0; j < 4; j++) cn4[j] = g_colnorm[bk0 + lane + 32 * j];

#pragma unroll 2
    for (int r = 0; r < 8; r++) {
        int lr = wid * 8 + r;
        int gr = bm0 + lr;
        float rn = g_rownorm[gr];
        const float* crow = &Cs[lr * CS_STRIDE];
        float* drow = outD + (size_t)gr * KCB + bk0;
        float v[4];
        float mn = 3.4e38f;
#pragma unroll
        for (int j = 0; j < 4; j++) {
            int c = lane + 32 * j;
            float d = (rn - crow[c]) + cn4[j];
            v[j] = d;
            drow[c] = d;
            if (d < mn) mn = d;
        }
#pragma unroll
        for (int off = 16; off > 0; off >>= 1) {
            float o = __shfl_xor_sync(0xFFFFFFFFu, mn, off);
            if (o < mn) mn = o;
        }
        float thr = mn + CAND_MARGIN;
#pragma unroll
        for (int j = 0; j < 4; j++) {
            if (v[j] <= thr) {
                int slot = atomicAdd(&g_candn[gr], 1);
                if (slot < CAND_CAP)
                    g_cand[gr][slot] = (unsigned short)(bk0 + lane + 32 * j);
            }
        }
    }
}

// ---------------------------------------------------------------------------
// rescue: block = 32 rows, 8 threads/row. Candidates processed serially by
// the 8-lane group (coalesced codebook reads), two at a time. Per-8-group
// shfl masks. Exact fp32 numerics. Writes indices, histogram, quantized.
// ---------------------------------------------------------------------------
#define RROWS 32   // rows per block
__global__ __launch_bounds__(256, 4) void rescue_k(const float* __restrict__ X,
                                                   const float* __restrict__ CB,
                                                   float* __restrict__ outI,
                                                   float* __restrict__ outQ) {
    __shared__ float Xs[RROWS * DIM];           // 8 KB
    const int tid = threadIdx.x;
    const int r = tid >> 3;        // 0..31 row within block
    const int s = tid & 7;         // lane within row group
    const int lane = tid & 31;
    const unsigned gmask = 0xFFu << (lane & 24);   // this 8-group's lanes
    const int row0 = blockIdx.x * RROWS;
    const int gr = row0 + r;

    // cooperative X stage: 32 rows x 64 floats = 512 float4
    {
        const float4* Xg = (const float4*)(X + (size_t)row0 * DIM);
        float4* Xs4 = (float4*)Xs;
#pragma unroll
        for (int i = 0; i < 2; i++) Xs4[tid + i * 256] = Xg[tid + i * 256];
    }
    __syncthreads();

    const float rn = g_rownorm[gr];
    const float4* xp4 = (const float4*)(Xs + r * DIM);
    const int n = g_candn[gr];

    unsigned long long best = 0xFFFFFFFFFFFFFFFFULL;
    if (n <= CAND_CAP) {
        float4 x0 = xp4[s * 2];
        float4 x1 = xp4[s * 2 + 1];
        int j = 0;
        for (; j + 1 < n; j += 2) {
            int c0 = g_cand[gr][j];
            int c1 = g_cand[gr][j + 1];
            const float4* e0p = (const float4*)(CB + (size_t)c0 * DIM);
            const float4* e1p = (const float4*)(CB + (size_t)c1 * DIM);
            float4 a0 = e0p[s * 2], a1 = e0p[s * 2 + 1];
            float4 b0 = e1p[s * 2], b1 = e1p[s * 2 + 1];
            float p = x0.x * a0.x;
            p = fmaf(x0.y, a0.y, p); p = fmaf(x0.z, a0.z, p);
            p = fmaf(x0.w, a0.w, p); p = fmaf(x1.x, a1.x, p);
            p = fmaf(x1.y, a1.y, p); p = fmaf(x1.z, a1.z, p);
            p = fmaf(x1.w, a1.w, p);
            float q = x0.x * b0.x;
            q = fmaf(x0.y, b0.y, q); q = fmaf(x0.z, b0.z, q);
            q = fmaf(x0.w, b0.w, q); q = fmaf(x1.x, b1.x, q);
            q = fmaf(x1.y, b1.y, q); q = fmaf(x1.z, b1.z, q);
            q = fmaf(x1.w, b1.w, q);
            p += __shfl_xor_sync(gmask, p, 4);
            q += __shfl_xor_sync(gmask, q, 4);
            p += __shfl_xor_sync(gmask, p, 2);
            q += __shfl_xor_sync(gmask, q, 2);
            p += __shfl_xor_sync(gmask, p, 1);
            q += __shfl_xor_sync(gmask, q, 1);
            float d0 = (rn - 2.f * p) + g_colnorm[c0];
            float d1 = (rn - 2.f * q) + g_colnorm[c1];
            unsigned long long k0 =
                ((unsigned long long)forder(d0) << 32) | (unsigned)c0;
            unsigned long long k1 =
                ((unsigned long long)forder(d1) << 32) | (unsigned)c1;
            if (k0 < best) best = k0;
            if (k1 < best) best = k1;
        }
        if (j < n) {
            int c0 = g_cand[gr][j];
            const float4* e0p = (const float4*)(CB + (size_t)c0 * DIM);
            float4 a0 = e0p[s * 2], a1 = e0p[s * 2 + 1];
            float p = x0.x * a0.x;
            p = fmaf(x0.y, a0.y, p); p = fmaf(x0.z, a0.z, p);
            p = fmaf(x0.w, a0.w, p); p = fmaf(x1.x, a1.x, p);
            p = fmaf(x1.y, a1.y, p); p = fmaf(x1.z, a1.z, p);
            p = fmaf(x1.w, a1.w, p);
            p += __shfl_xor_sync(gmask, p, 4);
            p += __shfl_xor_sync(gmask, p, 2);
            p += __shfl_xor_sync(gmask, p, 1);
            float d0 = (rn - 2.f * p) + g_colnorm[c0];
            unsigned long long k0 =
                ((unsigned long long)forder(d0) << 32) | (unsigned)c0;
            if (k0 < best) best = k0;
        }
    } else {
        // overflow fallback (rare): per-lane scan of all 512 codes
        for (int c = s; c < KCB; c += 8) {
            const float4* cp4 = (const float4*)(CB + (size_t)c * DIM);
            float d0 = 0.f, d1 = 0.f, d2 = 0.f, d3 = 0.f;
#pragma unroll
            for (int i = 0; i < DIM / 4; i++) {
                float4 x = xp4[i];
                float4 e = cp4[i];
                d0 = fmaf(x.x, e.x, d0);
                d1 = fmaf(x.y, e.y, d1);
                d2 = fmaf(x.z, e.z, d2);
                d3 = fmaf(x.w, e.w, d3);
            }
            float dot = (d0 + d1) + (d2 + d3);
            float d = (rn - 2.f * dot) + g_colnorm[c];
            unsigned long long key =
                ((unsigned long long)forder(d) << 32) | (unsigned)c;
            if (key < best) best = key;
        }
#pragma unroll
        for (int off = 4; off > 0; off >>= 1) {
            unsigned long long o = __shfl_xor_sync(gmask, best, off);
            if (o < best) best = o;
        }
    }
    int idx = (int)(best & 0xFFFFFFFFu);

    if (s == 0) {
        outI[gr] = (float)idx;
        atomicAdd(&g_count[idx], 1u);
    }

    // quantized: 8 threads x 8 floats (2 float4 each); outQ 16B-aligned
    {
        const float4* cp4 = (const float4*)(CB + (size_t)idx * DIM);
        float4* qp4 = (float4*)(outQ + (size_t)gr * DIM);
#pragma unroll
        for (int i = 0; i < 2; i++) {
            int j = s * 2 + i;
            float4 x = xp4[j];
            float4 e = cp4[j];
            float4 q;
            q.x = x.x + (e.x - x.x);
            q.y = x.y + (e.y - x.y);
            q.z = x.z + (e.z - x.z);
            q.w = x.w + (e.w - x.w);
            qp4[j] = q;
        }
    }
}

// ---------------------------------------------------------------------------
// ewrite: pure streaming one-hot writer. One warp per row; full row written
// (no pre-zeroing). Minimal registers -> max occupancy -> near-peak DRAM BW.
// ---------------------------------------------------------------------------
__global__ __launch_bounds__(256) void ewrite_k(const float* __restrict__ outI,
                                                float* __restrict__ outE) {
    int warp = blockIdx.x * 8 + (threadIdx.x >> 5);
    int lane = threadIdx.x & 31;
    int idx = (int)__ldg(&outI[warp]);
    float* ep = outE + (size_t)warp * KCB;
#pragma unroll
    for (int j = 0; j < 16; j++) {
        int col = j * 32 + lane;
        ep[col] = (col == idx) ? 1.f : 0.f;
    }
}

// ---------------------------------------------------------------------------
__global__ void perp_k(float* __restrict__ outP) {
    __shared__ float s[KCB];
    int t = threadIdx.x;
    float p = (float)g_count[t] / (float)N_ROWS;
    s[t] = p * logf(p + 1e-10f);
    __syncthreads();
    for (int o = KCB / 2; o > 0; o >>= 1) {
        if (t < o) s[t] += s[t + o];
        __syncthreads();
    }
    if (t == 0) outP[0] = expf(-s[0]);
}

// ---------------------------------------------------------------------------
extern "C" void kernel_launch(void* const* d_in, const int* in_sizes, int n_in,
                              void* d_out, int out_size) {
    const float* X = (const float*)d_in[0];
    const float* CB = (const float*)d_in[1];
    if (n_in >= 2 && in_sizes[0] == KCB * DIM) {
        X = (const float*)d_in[1];
        CB = (const float*)d_in[0];
    }
    float* out = (float*)d_out;
    float* outQ = out + OFF_Q;
    float* outP = out + OFF_P;
    float* outE = out + OFF_E;
    float* outI = out + OFF_I;
    float* outD = out + OFF_D;

    cudaFuncSetAttribute(gemm_k, cudaFuncAttributeMaxDynamicSharedMemorySize,
                         GEMM_SMEM_BYTES);

    rownorm_k<<<N_ROWS / 256, 256>>>(X);
    colnorm_k<<<2, 256>>>(CB);
    dim3 ggrid(KCB / 128, N_ROWS / 64 / 2);
    gemm_k<<<ggrid, 256, GEMM_SMEM_BYTES>>>(X, CB, outD, 0);
    gemm_k<<<ggrid, 256, GEMM_SMEM_BYTES>>>(X, CB, outD, N_ROWS / 2);
    rescue_k<<<N_ROWS / RROWS, 256>>>(X, CB, outI, outQ);
    ewrite_k<<<N_ROWS / 8, 256>>>(outI, outE);
    perp_k<<<1, KCB>>>(outP);
}

// round 13
// speedup vs baseline: 1.2941x; 1.0974x over previous
#include <cuda_runtime.h>
#include <cuda_bf16.h>
#include <math.h>

#define N_ROWS 131072   // 32*64*64
#define DIM    64
#define KCB    512

// Output layout (concatenated, float32). Scalar perplexity misaligns
// everything after it to 4B -> scalar stores only into outE/outD.
#define OFF_Q 0
#define OFF_P (N_ROWS * DIM)
#define OFF_E (OFF_P + 1)
#define OFF_I (OFF_E + (size_t)N_ROWS * KCB)
#define OFF_D (OFF_I + N_ROWS)

#define CAND_CAP 16
#define CAND_MARGIN 1.2e-3f   // ~30x measured bf16 distance error (4e-5)

// Scratch
__device__ float g_rownorm[N_ROWS];
__device__ float g_colnorm[KCB];
__device__ unsigned int g_count[KCB];
__device__ int g_candn[N_ROWS];
__device__ unsigned short g_cand[N_ROWS][CAND_CAP];

// ---------------------------------------------------------------------------
__device__ __forceinline__ unsigned int forder(float f) {
    unsigned int u = __float_as_uint(f);
    unsigned int mask = ((int)u >> 31) | 0x80000000u;
    return u ^ mask;  // monotonic float -> uint
}

// pack two floats into bf16x2: lo half = first element (lower k), hi = second
__device__ __forceinline__ unsigned pack_bf16x2(float lo, float hi) {
    unsigned r;
    asm("cvt.rn.bf16x2.f32 %0, %1, %2;" : "=r"(r) : "f"(hi), "f"(lo));
    return r;
}

// m16n8k16 bf16 MMA, fp32 accumulate
__device__ __forceinline__ void mma16(float* c, unsigned a0, unsigned a1,
                                      unsigned a2, unsigned a3,
                                      unsigned b0, unsigned b1) {
    asm volatile(
        "mma.sync.aligned.m16n8k16.row.col.f32.bf16.bf16.f32 "
        "{%0,%1,%2,%3}, {%4,%5,%6,%7}, {%8,%9}, {%0,%1,%2,%3};"
        : "+f"(c[0]), "+f"(c[1]), "+f"(c[2]), "+f"(c[3])
        : "r"(a0), "r"(a1), "r"(a2), "r"(a3), "r"(b0), "r"(b1));
}

// ---------------------------------------------------------------------------
__global__ void rownorm_k(const float* __restrict__ X) {
    int r = blockIdx.x * blockDim.x + threadIdx.x;
    if (r >= N_ROWS) return;
    g_candn[r] = 0;
    const float4* p = (const float4*)(X + (size_t)r * DIM);
    float s = 0.f;
#pragma unroll
    for (int i = 0; i < DIM / 4; i++) {
        float4 v = p[i];
        s += v.x * v.x + v.y * v.y + v.z * v.z + v.w * v.w;
    }
    g_rownorm[r] = s;
}

__global__ void colnorm_k(const float* __restrict__ CB) {
    int r = blockIdx.x * blockDim.x + threadIdx.x;
    if (r >= KCB) return;
    g_count[r] = 0u;
    const float4* p = (const float4*)(CB + (size_t)r * DIM);
    float s = 0.f;
#pragma unroll
    for (int i = 0; i < DIM / 4; i++) {
        float4 v = p[i];
        s += v.x * v.x + v.y * v.y + v.z * v.z + v.w * v.w;
    }
    g_colnorm[r] = s;
}

// ---------------------------------------------------------------------------
// bf16 tensor-core distance GEMM (m16n8k16) + candidate collection.
// CTA 64x128, K=64 resident, 8 warps, 32x32/warp. k-PAIR permuted smem
// layout: within each 16-k block, pair p -> slot (p&3)*2 + (p>>2); thread t's
// fragment pairs {t, t+4} are one LDS.64 ({a0,a2}, {a1,a3}, {b0,b1}).
// 4 CTAs/SM target (<=64 regs): B fragments loaded per-ni to keep live
// range at 2 regs. Exact argmin protected by the fp32 rescue pass.
// ---------------------------------------------------------------------------
#define ROW_BYTES 160
#define AS_BYTES (64 * ROW_BYTES)      // 10240
#define CS_STRIDE 132
#define GEMM_SMEM_BYTES (64 * CS_STRIDE * 4)   // 33792 >= 30720 operand bytes

__global__ __launch_bounds__(256, 4) void gemm_k(const float* __restrict__ A,
                                                 const float* __restrict__ B,
                                                 float* __restrict__ outD,
                                                 int bm_base) {
    extern __shared__ char smc[];
    char* As = smc;                 // [64 rows][160B] bf16, pair-permuted
    char* Bs = smc + AS_BYTES;      // [128 rows][160B] bf16(2*codebook)
    float* Cs = (float*)smc;        // [64][132] fp32, aliases post-MMA

    const int tid = threadIdx.x;
    const int lane = tid & 31;
    const int wid = tid >> 5;
    const int g = lane >> 2;
    const int t = lane & 3;
    const int wm0 = (wid & 1) * 32;      // 2 warp rows
    const int wn0 = (wid >> 1) * 32;     // 4 warp cols
    const int bm0 = bm_base + blockIdx.y * 64;
    const int bk0 = blockIdx.x * 128;

    // Tile load: fp32 -> bf16 cvt + k-pair-permuted scatter.
    {
        const float4* Ag = (const float4*)(A + (size_t)bm0 * DIM);
        const float4* Bg = (const float4*)(B + (size_t)bk0 * DIM);
#pragma unroll
        for (int i = 0; i < 4; i++) {          // A: 64 rows = 1024 float4
            int t4 = tid + i * 256;
            int row = t4 >> 4;
            int c4 = (t4 & 15) * 4;
            int kblk = c4 >> 4;
            int p0 = (c4 & 15) >> 1;           // 0,2,4,6
            int s0 = ((p0 & 3) << 1) | (p0 >> 2);
            int s1 = (((p0 + 1) & 3) << 1) | ((p0 + 1) >> 2);
            char* rp = As + row * ROW_BYTES + kblk * 32;
            float4 va = Ag[t4];
            *(unsigned*)(rp + s0 * 4) = pack_bf16x2(va.x, va.y);
            *(unsigned*)(rp + s1 * 4) = pack_bf16x2(va.z, va.w);
        }
#pragma unroll
        for (int i = 0; i < 8; i++) {          // B: 128 rows = 2048 float4
            int t4 = tid + i * 256;
            int row = t4 >> 4;
            int c4 = (t4 & 15) * 4;
            int kblk = c4 >> 4;
            int p0 = (c4 & 15) >> 1;
            int s0 = ((p0 & 3) << 1) | (p0 >> 2);
            int s1 = (((p0 + 1) & 3) << 1) | ((p0 + 1) >> 2);
            char* rp = Bs + row * ROW_BYTES + kblk * 32;
            float4 vb = Bg[t4];
            *(unsigned*)(rp + s0 * 4) = pack_bf16x2(2.f * vb.x, 2.f * vb.y);
            *(unsigned*)(rp + s1 * 4) = pack_bf16x2(2.f * vb.z, 2.f * vb.w);
        }
    }
    __syncthreads();

    float acc[2][4][4];
#pragma unroll
    for (int mi = 0; mi < 2; mi++)
#pragma unroll
        for (int ni = 0; ni < 4; ni++)
#pragma unroll
            for (int j = 0; j < 4; j++) acc[mi][ni][j] = 0.f;

#pragma unroll
    for (int kt = 0; kt < 4; kt++) {           // 4 k-tiles of 16
        const int kb = kt * 32 + t * 8;
        uint2 fa[2][2];
#pragma unroll
        for (int mi = 0; mi < 2; mi++) {
            int r0 = wm0 + mi * 16 + g;
            fa[mi][0] = *(const uint2*)(As + r0 * ROW_BYTES + kb);        // {a0,a2}
            fa[mi][1] = *(const uint2*)(As + (r0 + 8) * ROW_BYTES + kb);  // {a1,a3}
        }
#pragma unroll
        for (int ni = 0; ni < 4; ni++) {       // fb live range = 2 regs
            int n = wn0 + ni * 8 + g;
            uint2 fb = *(const uint2*)(Bs + n * ROW_BYTES + kb);          // {b0,b1}
#pragma unroll
            for (int mi = 0; mi < 2; mi++)
                mma16(acc[mi][ni], fa[mi][0].x, fa[mi][1].x,
                      fa[mi][0].y, fa[mi][1].y, fb.x, fb.y);
        }
    }

    __syncthreads();
    // Stage accumulators via STS.64 (c0 even -> 8B aligned)
#pragma unroll
    for (int mi = 0; mi < 2; mi++)
#pragma unroll
        for (int ni = 0; ni < 4; ni++) {
            int r0 = wm0 + mi * 16 + g;
            int c0 = wn0 + ni * 8 + 2 * t;
            *(float2*)&Cs[r0 * CS_STRIDE + c0] =
                make_float2(acc[mi][ni][0], acc[mi][ni][1]);
            *(float2*)&Cs[(r0 + 8) * CS_STRIDE + c0] =
                make_float2(acc[mi][ni][2], acc[mi][ni][3]);
        }
    __syncthreads();

    // Distance stores + candidate collection. 8 warps x 8 rows = 64 rows.
    float cn4[4];
#pragma unroll
    for (int j = 0; j < 4; j++) cn4[j] = g_colnorm[bk0 + lane + 32 * j];

#pragma unroll 2
    for (int r = 0; r < 8; r++) {
        int lr = wid * 8 + r;
        int gr = bm0 + lr;
        float rn = g_rownorm[gr];
        const float* crow = &Cs[lr * CS_STRIDE];
        float* drow = outD + (size_t)gr * KCB + bk0;
        float v[4];
        float mn = 3.4e38f;
#pragma unroll
        for (int j = 0; j < 4; j++) {
            int c = lane + 32 * j;
            float d = (rn - crow[c]) + cn4[j];
            v[j] = d;
            drow[c] = d;
            if (d < mn) mn = d;
        }
#pragma unroll
        for (int off = 16; off > 0; off >>= 1) {
            float o = __shfl_xor_sync(0xFFFFFFFFu, mn, off);
            if (o < mn) mn = o;
        }
        float thr = mn + CAND_MARGIN;
#pragma unroll
        for (int j = 0; j < 4; j++) {
            if (v[j] <= thr) {
                int slot = atomicAdd(&g_candn[gr], 1);
                if (slot < CAND_CAP)
                    g_cand[gr][slot] = (unsigned short)(bk0 + lane + 32 * j);
            }
        }
    }
}

// ---------------------------------------------------------------------------
// rescue: block = 32 rows, 8 threads/row. Candidates processed serially by
// the 8-lane group (coalesced codebook reads), two at a time. Per-8-group
// shfl masks. Exact fp32 numerics. Writes indices, histogram, quantized.
// ---------------------------------------------------------------------------
#define RROWS 32   // rows per block
__global__ __launch_bounds__(256, 4) void rescue_k(const float* __restrict__ X,
                                                   const float* __restrict__ CB,
                                                   float* __restrict__ outI,
                                                   float* __restrict__ outQ) {
    __shared__ float Xs[RROWS * DIM];           // 8 KB
    const int tid = threadIdx.x;
    const int r = tid >> 3;        // 0..31 row within block
    const int s = tid & 7;         // lane within row group
    const int lane = tid & 31;
    const unsigned gmask = 0xFFu << (lane & 24);   // this 8-group's lanes
    const int row0 = blockIdx.x * RROWS;
    const int gr = row0 + r;

    // cooperative X stage: 32 rows x 64 floats = 512 float4
    {
        const float4* Xg = (const float4*)(X + (size_t)row0 * DIM);
        float4* Xs4 = (float4*)Xs;
#pragma unroll
        for (int i = 0; i < 2; i++) Xs4[tid + i * 256] = Xg[tid + i * 256];
    }
    __syncthreads();

    const float rn = g_rownorm[gr];
    const float4* xp4 = (const float4*)(Xs + r * DIM);
    const int n = g_candn[gr];

    unsigned long long best = 0xFFFFFFFFFFFFFFFFULL;
    if (n <= CAND_CAP) {
        float4 x0 = xp4[s * 2];
        float4 x1 = xp4[s * 2 + 1];
        int j = 0;
        for (; j + 1 < n; j += 2) {
            int c0 = g_cand[gr][j];
            int c1 = g_cand[gr][j + 1];
            const float4* e0p = (const float4*)(CB + (size_t)c0 * DIM);
            const float4* e1p = (const float4*)(CB + (size_t)c1 * DIM);
            float4 a0 = e0p[s * 2], a1 = e0p[s * 2 + 1];
            float4 b0 = e1p[s * 2], b1 = e1p[s * 2 + 1];
            float p = x0.x * a0.x;
            p = fmaf(x0.y, a0.y, p); p = fmaf(x0.z, a0.z, p);
            p = fmaf(x0.w, a0.w, p); p = fmaf(x1.x, a1.x, p);
            p = fmaf(x1.y, a1.y, p); p = fmaf(x1.z, a1.z, p);
            p = fmaf(x1.w, a1.w, p);
            float q = x0.x * b0.x;
            q = fmaf(x0.y, b0.y, q); q = fmaf(x0.z, b0.z, q);
            q = fmaf(x0.w, b0.w, q); q = fmaf(x1.x, b1.x, q);
            q = fmaf(x1.y, b1.y, q); q = fmaf(x1.z, b1.z, q);
            q = fmaf(x1.w, b1.w, q);
            p += __shfl_xor_sync(gmask, p, 4);
            q += __shfl_xor_sync(gmask, q, 4);
            p += __shfl_xor_sync(gmask, p, 2);
            q += __shfl_xor_sync(gmask, q, 2);
            p += __shfl_xor_sync(gmask, p, 1);
            q += __shfl_xor_sync(gmask, q, 1);
            float d0 = (rn - 2.f * p) + g_colnorm[c0];
            float d1 = (rn - 2.f * q) + g_colnorm[c1];
            unsigned long long k0 =
                ((unsigned long long)forder(d0) << 32) | (unsigned)c0;
            unsigned long long k1 =
                ((unsigned long long)forder(d1) << 32) | (unsigned)c1;
            if (k0 < best) best = k0;
            if (k1 < best) best = k1;
        }
        if (j < n) {
            int c0 = g_cand[gr][j];
            const float4* e0p = (const float4*)(CB + (size_t)c0 * DIM);
            float4 a0 = e0p[s * 2], a1 = e0p[s * 2 + 1];
            float p = x0.x * a0.x;
            p = fmaf(x0.y, a0.y, p); p = fmaf(x0.z, a0.z, p);
            p = fmaf(x0.w, a0.w, p); p = fmaf(x1.x, a1.x, p);
            p = fmaf(x1.y, a1.y, p); p = fmaf(x1.z, a1.z, p);
            p = fmaf(x1.w, a1.w, p);
            p += __shfl_xor_sync(gmask, p, 4);
            p += __shfl_xor_sync(gmask, p, 2);
            p += __shfl_xor_sync(gmask, p, 1);
            float d0 = (rn - 2.f * p) + g_colnorm[c0];
            unsigned long long k0 =
                ((unsigned long long)forder(d0) << 32) | (unsigned)c0;
            if (k0 < best) best = k0;
        }
    } else {
        // overflow fallback (rare): per-lane scan of all 512 codes
        for (int c = s; c < KCB; c += 8) {
            const float4* cp4 = (const float4*)(CB + (size_t)c * DIM);
            float d0 = 0.f, d1 = 0.f, d2 = 0.f, d3 = 0.f;
#pragma unroll
            for (int i = 0; i < DIM / 4; i++) {
                float4 x = xp4[i];
                float4 e = cp4[i];
                d0 = fmaf(x.x, e.x, d0);
                d1 = fmaf(x.y, e.y, d1);
                d2 = fmaf(x.z, e.z, d2);
                d3 = fmaf(x.w, e.w, d3);
            }
            float dot = (d0 + d1) + (d2 + d3);
            float d = (rn - 2.f * dot) + g_colnorm[c];
            unsigned long long key =
                ((unsigned long long)forder(d) << 32) | (unsigned)c;
            if (key < best) best = key;
        }
#pragma unroll
        for (int off = 4; off > 0; off >>= 1) {
            unsigned long long o = __shfl_xor_sync(gmask, best, off);
            if (o < best) best = o;
        }
    }
    int idx = (int)(best & 0xFFFFFFFFu);

    if (s == 0) {
        outI[gr] = (float)idx;
        atomicAdd(&g_count[idx], 1u);
    }

    // quantized: 8 threads x 8 floats (2 float4 each); outQ 16B-aligned
    {
        const float4* cp4 = (const float4*)(CB + (size_t)idx * DIM);
        float4* qp4 = (float4*)(outQ + (size_t)gr * DIM);
#pragma unroll
        for (int i = 0; i < 2; i++) {
            int j = s * 2 + i;
            float4 x = xp4[j];
            float4 e = cp4[j];
            float4 q;
            q.x = x.x + (e.x - x.x);
            q.y = x.y + (e.y - x.y);
            q.z = x.z + (e.z - x.z);
            q.w = x.w + (e.w - x.w);
            qp4[j] = q;
        }
    }
}

// ---------------------------------------------------------------------------
// ewrite: pure streaming one-hot writer. One warp per row; full row written
// (no pre-zeroing). Minimal registers -> max occupancy -> near-peak DRAM BW.
// ---------------------------------------------------------------------------
__global__ __launch_bounds__(256) void ewrite_k(const float* __restrict__ outI,
                                                float* __restrict__ outE) {
    int warp = blockIdx.x * 8 + (threadIdx.x >> 5);
    int lane = threadIdx.x & 31;
    int idx = (int)__ldg(&outI[warp]);
    float* ep = outE + (size_t)warp * KCB;
#pragma unroll
    for (int j = 0; j < 16; j++) {
        int col = j * 32 + lane;
        ep[col] = (col == idx) ? 1.f : 0.f;
    }
}

// ---------------------------------------------------------------------------
__global__ void perp_k(float* __restrict__ outP) {
    __shared__ float s[KCB];
    int t = threadIdx.x;
    float p = (float)g_count[t] / (float)N_ROWS;
    s[t] = p * logf(p + 1e-10f);
    __syncthreads();
    for (int o = KCB / 2; o > 0; o >>= 1) {
        if (t < o) s[t] += s[t + o];
        __syncthreads();
    }
    if (t == 0) outP[0] = expf(-s[0]);
}

// ---------------------------------------------------------------------------
extern "C" void kernel_launch(void* const* d_in, const int* in_sizes, int n_in,
                              void* d_out, int out_size) {
    const float* X = (const float*)d_in[0];
    const float* CB = (const float*)d_in[1];
    if (n_in >= 2 && in_sizes[0] == KCB * DIM) {
        X = (const float*)d_in[1];
        CB = (const float*)d_in[0];
    }
    float* out = (float*)d_out;
    float* outQ = out + OFF_Q;
    float* outP = out + OFF_P;
    float* outE = out + OFF_E;
    float* outI = out + OFF_I;
    float* outD = out + OFF_D;

    cudaFuncSetAttribute(gemm_k, cudaFuncAttributeMaxDynamicSharedMemorySize,
                         GEMM_SMEM_BYTES);

    rownorm_k<<<N_ROWS / 256, 256>>>(X);
    colnorm_k<<<2, 256>>>(CB);
    dim3 ggrid(KCB / 128, N_ROWS / 64 / 2);
    gemm_k<<<ggrid, 256, GEMM_SMEM_BYTES>>>(X, CB, outD, 0);
    gemm_k<<<ggrid, 256, GEMM_SMEM_BYTES>>>(X, CB, outD, N_ROWS / 2);
    rescue_k<<<N_ROWS / RROWS, 256>>>(X, CB, outI, outQ);
    ewrite_k<<<N_ROWS / 8, 256>>>(outI, outE);
    perp_k<<<1, KCB>>>(outP);
}

// round 14
// speedup vs baseline: 1.3388x; 1.0346x over previous
#include <cuda_runtime.h>
#include <cuda_bf16.h>
#include <math.h>

#define N_ROWS 131072   // 32*64*64
#define DIM    64
#define KCB    512

// Output layout (concatenated, float32). Scalar perplexity misaligns
// everything after it to 4B -> scalar stores only into outE/outD.
#define OFF_Q 0
#define OFF_P (N_ROWS * DIM)
#define OFF_E (OFF_P + 1)
#define OFF_I (OFF_E + (size_t)N_ROWS * KCB)
#define OFF_D (OFF_I + N_ROWS)

#define CAND_CAP 16
#define CAND_MARGIN 1.2e-3f   // ~30x measured bf16 distance error (4e-5)

// Scratch
__device__ float g_rownorm[N_ROWS];
__device__ float g_colnorm[KCB];
__device__ unsigned int g_count[KCB];
__device__ int g_candn[N_ROWS];
__device__ unsigned short g_cand[N_ROWS][CAND_CAP];

// ---------------------------------------------------------------------------
__device__ __forceinline__ unsigned int forder(float f) {
    unsigned int u = __float_as_uint(f);
    unsigned int mask = ((int)u >> 31) | 0x80000000u;
    return u ^ mask;  // monotonic float -> uint
}

// pack two floats into bf16x2: lo half = first element (lower k), hi = second
__device__ __forceinline__ unsigned pack_bf16x2(float lo, float hi) {
    unsigned r;
    asm("cvt.rn.bf16x2.f32 %0, %1, %2;" : "=r"(r) : "f"(hi), "f"(lo));
    return r;
}

// m16n8k16 bf16 MMA, fp32 accumulate
__device__ __forceinline__ void mma16(float* c, unsigned a0, unsigned a1,
                                      unsigned a2, unsigned a3,
                                      unsigned b0, unsigned b1) {
    asm volatile(
        "mma.sync.aligned.m16n8k16.row.col.f32.bf16.bf16.f32 "
        "{%0,%1,%2,%3}, {%4,%5,%6,%7}, {%8,%9}, {%0,%1,%2,%3};"
        : "+f"(c[0]), "+f"(c[1]), "+f"(c[2]), "+f"(c[3])
        : "r"(a0), "r"(a1), "r"(a2), "r"(a3), "r"(b0), "r"(b1));
}

// ---------------------------------------------------------------------------
__global__ void rownorm_k(const float* __restrict__ X) {
    int r = blockIdx.x * blockDim.x + threadIdx.x;
    if (r >= N_ROWS) return;
    g_candn[r] = 0;
    const float4* p = (const float4*)(X + (size_t)r * DIM);
    float s = 0.f;
#pragma unroll
    for (int i = 0; i < DIM / 4; i++) {
        float4 v = p[i];
        s += v.x * v.x + v.y * v.y + v.z * v.z + v.w * v.w;
    }
    g_rownorm[r] = s;
}

__global__ void colnorm_k(const float* __restrict__ CB) {
    int r = blockIdx.x * blockDim.x + threadIdx.x;
    if (r >= KCB) return;
    g_count[r] = 0u;
    const float4* p = (const float4*)(CB + (size_t)r * DIM);
    float s = 0.f;
#pragma unroll
    for (int i = 0; i < DIM / 4; i++) {
        float4 v = p[i];
        s += v.x * v.x + v.y * v.y + v.z * v.z + v.w * v.w;
    }
    g_colnorm[r] = s;
}

// ---------------------------------------------------------------------------
// bf16 tensor-core distance GEMM (m16n8k16) + candidate collection.
// CTA 64x128, K=64 resident, 8 warps, 32x32/warp. k-PAIR permuted smem
// layout: within each 16-k block, pair p -> slot (p&3)*2 + (p>>2); thread t's
// fragment pairs {t, t+4} are one LDS.64 ({a0,a2}, {a1,a3}, {b0,b1}).
// 4 CTAs/SM (<=64 regs). Exact argmin protected by the fp32 rescue pass.
// ---------------------------------------------------------------------------
#define ROW_BYTES 160
#define AS_BYTES (64 * ROW_BYTES)      // 10240
#define CS_STRIDE 132
#define GEMM_SMEM_BYTES (64 * CS_STRIDE * 4)   // 33792 >= 30720 operand bytes

__global__ __launch_bounds__(256, 4) void gemm_k(const float* __restrict__ A,
                                                 const float* __restrict__ B,
                                                 float* __restrict__ outD) {
    extern __shared__ char smc[];
    char* As = smc;                 // [64 rows][160B] bf16, pair-permuted
    char* Bs = smc + AS_BYTES;      // [128 rows][160B] bf16(2*codebook)
    float* Cs = (float*)smc;        // [64][132] fp32, aliases post-MMA

    const int tid = threadIdx.x;
    const int lane = tid & 31;
    const int wid = tid >> 5;
    const int g = lane >> 2;
    const int t = lane & 3;
    const int wm0 = (wid & 1) * 32;      // 2 warp rows
    const int wn0 = (wid >> 1) * 32;     // 4 warp cols
    const int bm0 = blockIdx.y * 64;
    const int bk0 = blockIdx.x * 128;

    // Tile load: fp32 -> bf16 cvt + k-pair-permuted scatter.
    {
        const float4* Ag = (const float4*)(A + (size_t)bm0 * DIM);
        const float4* Bg = (const float4*)(B + (size_t)bk0 * DIM);
#pragma unroll
        for (int i = 0; i < 4; i++) {          // A: 64 rows = 1024 float4
            int t4 = tid + i * 256;
            int row = t4 >> 4;
            int c4 = (t4 & 15) * 4;
            int kblk = c4 >> 4;
            int p0 = (c4 & 15) >> 1;           // 0,2,4,6
            int s0 = ((p0 & 3) << 1) | (p0 >> 2);
            int s1 = (((p0 + 1) & 3) << 1) | ((p0 + 1) >> 2);
            char* rp = As + row * ROW_BYTES + kblk * 32;
            float4 va = Ag[t4];
            *(unsigned*)(rp + s0 * 4) = pack_bf16x2(va.x, va.y);
            *(unsigned*)(rp + s1 * 4) = pack_bf16x2(va.z, va.w);
        }
#pragma unroll
        for (int i = 0; i < 8; i++) {          // B: 128 rows = 2048 float4
            int t4 = tid + i * 256;
            int row = t4 >> 4;
            int c4 = (t4 & 15) * 4;
            int kblk = c4 >> 4;
            int p0 = (c4 & 15) >> 1;
            int s0 = ((p0 & 3) << 1) | (p0 >> 2);
            int s1 = (((p0 + 1) & 3) << 1) | ((p0 + 1) >> 2);
            char* rp = Bs + row * ROW_BYTES + kblk * 32;
            float4 vb = Bg[t4];
            *(unsigned*)(rp + s0 * 4) = pack_bf16x2(2.f * vb.x, 2.f * vb.y);
            *(unsigned*)(rp + s1 * 4) = pack_bf16x2(2.f * vb.z, 2.f * vb.w);
        }
    }
    __syncthreads();

    float acc[2][4][4];
#pragma unroll
    for (int mi = 0; mi < 2; mi++)
#pragma unroll
        for (int ni = 0; ni < 4; ni++)
#pragma unroll
            for (int j = 0; j < 4; j++) acc[mi][ni][j] = 0.f;

#pragma unroll
    for (int kt = 0; kt < 4; kt++) {           // 4 k-tiles of 16
        const int kb = kt * 32 + t * 8;
        uint2 fa[2][2];
#pragma unroll
        for (int mi = 0; mi < 2; mi++) {
            int r0 = wm0 + mi * 16 + g;
            fa[mi][0] = *(const uint2*)(As + r0 * ROW_BYTES + kb);        // {a0,a2}
            fa[mi][1] = *(const uint2*)(As + (r0 + 8) * ROW_BYTES + kb);  // {a1,a3}
        }
#pragma unroll
        for (int ni = 0; ni < 4; ni++) {       // fb live range = 2 regs
            int n = wn0 + ni * 8 + g;
            uint2 fb = *(const uint2*)(Bs + n * ROW_BYTES + kb);          // {b0,b1}
#pragma unroll
            for (int mi = 0; mi < 2; mi++)
                mma16(acc[mi][ni], fa[mi][0].x, fa[mi][1].x,
                      fa[mi][0].y, fa[mi][1].y, fb.x, fb.y);
        }
    }

    __syncthreads();
    // Stage accumulators via STS.64 (c0 even -> 8B aligned)
#pragma unroll
    for (int mi = 0; mi < 2; mi++)
#pragma unroll
        for (int ni = 0; ni < 4; ni++) {
            int r0 = wm0 + mi * 16 + g;
            int c0 = wn0 + ni * 8 + 2 * t;
            *(float2*)&Cs[r0 * CS_STRIDE + c0] =
                make_float2(acc[mi][ni][0], acc[mi][ni][1]);
            *(float2*)&Cs[(r0 + 8) * CS_STRIDE + c0] =
                make_float2(acc[mi][ni][2], acc[mi][ni][3]);
        }
    __syncthreads();

    // Distance stores + candidate collection. 8 warps x 8 rows = 64 rows.
    float cn4[4];
#pragma unroll
    for (int j = 0; j < 4; j++) cn4[j] = g_colnorm[bk0 + lane + 32 * j];

#pragma unroll 2
    for (int r = 0; r < 8; r++) {
        int lr = wid * 8 + r;
        int gr = bm0 + lr;
        float rn = g_rownorm[gr];
        const float* crow = &Cs[lr * CS_STRIDE];
        float* drow = outD + (size_t)gr * KCB + bk0;
        float v[4];
        float mn = 3.4e38f;
#pragma unroll
        for (int j = 0; j < 4; j++) {
            int c = lane + 32 * j;
            float d = (rn - crow[c]) + cn4[j];
            v[j] = d;
            drow[c] = d;
            if (d < mn) mn = d;
        }
#pragma unroll
        for (int off = 16; off > 0; off >>= 1) {
            float o = __shfl_xor_sync(0xFFFFFFFFu, mn, off);
            if (o < mn) mn = o;
        }
        float thr = mn + CAND_MARGIN;
#pragma unroll
        for (int j = 0; j < 4; j++) {
            if (v[j] <= thr) {
                int slot = atomicAdd(&g_candn[gr], 1);
                if (slot < CAND_CAP)
                    g_cand[gr][slot] = (unsigned short)(bk0 + lane + 32 * j);
            }
        }
    }
}

// ---------------------------------------------------------------------------
// rescue + outputs: block = 32 rows, 8 threads/row. Candidates processed
// serially by the 8-lane group (coalesced codebook reads), two at a time.
// Per-8-group shfl masks. Exact fp32 numerics. Writes indices, histogram,
// quantized — then, after staging the 32 row indices in smem, the block
// re-partitions (warp = 4 rows) and streams the FULL one-hot rows with
// fully-coalesced 32-lane stores (hides the encodings DRAM traffic under
// this kernel's latency instead of a separate ewrite pass).
// ---------------------------------------------------------------------------
#define RROWS 32   // rows per block
__global__ __launch_bounds__(256, 4) void rescue_k(const float* __restrict__ X,
                                                   const float* __restrict__ CB,
                                                   float* __restrict__ outI,
                                                   float* __restrict__ outQ,
                                                   float* __restrict__ outE) {
    __shared__ float Xs[RROWS * DIM];           // 8 KB
    __shared__ int sidx[RROWS];
    const int tid = threadIdx.x;
    const int r = tid >> 3;        // 0..31 row within block
    const int s = tid & 7;         // lane within row group
    const int lane = tid & 31;
    const unsigned gmask = 0xFFu << (lane & 24);   // this 8-group's lanes
    const int row0 = blockIdx.x * RROWS;
    const int gr = row0 + r;

    // cooperative X stage: 32 rows x 64 floats = 512 float4
    {
        const float4* Xg = (const float4*)(X + (size_t)row0 * DIM);
        float4* Xs4 = (float4*)Xs;
#pragma unroll
        for (int i = 0; i < 2; i++) Xs4[tid + i * 256] = Xg[tid + i * 256];
    }
    __syncthreads();

    const float rn = g_rownorm[gr];
    const float4* xp4 = (const float4*)(Xs + r * DIM);
    const int n = g_candn[gr];

    unsigned long long best = 0xFFFFFFFFFFFFFFFFULL;
    if (n <= CAND_CAP) {
        float4 x0 = xp4[s * 2];
        float4 x1 = xp4[s * 2 + 1];
        int j = 0;
        for (; j + 1 < n; j += 2) {
            int c0 = g_cand[gr][j];
            int c1 = g_cand[gr][j + 1];
            const float4* e0p = (const float4*)(CB + (size_t)c0 * DIM);
            const float4* e1p = (const float4*)(CB + (size_t)c1 * DIM);
            float4 a0 = e0p[s * 2], a1 = e0p[s * 2 + 1];
            float4 b0 = e1p[s * 2], b1 = e1p[s * 2 + 1];
            float p = x0.x * a0.x;
            p = fmaf(x0.y, a0.y, p); p = fmaf(x0.z, a0.z, p);
            p = fmaf(x0.w, a0.w, p); p = fmaf(x1.x, a1.x, p);
            p = fmaf(x1.y, a1.y, p); p = fmaf(x1.z, a1.z, p);
            p = fmaf(x1.w, a1.w, p);
            float q = x0.x * b0.x;
            q = fmaf(x0.y, b0.y, q); q = fmaf(x0.z, b0.z, q);
            q = fmaf(x0.w, b0.w, q); q = fmaf(x1.x, b1.x, q);
            q = fmaf(x1.y, b1.y, q); q = fmaf(x1.z, b1.z, q);
            q = fmaf(x1.w, b1.w, q);
            p += __shfl_xor_sync(gmask, p, 4);
            q += __shfl_xor_sync(gmask, q, 4);
            p += __shfl_xor_sync(gmask, p, 2);
            q += __shfl_xor_sync(gmask, q, 2);
            p += __shfl_xor_sync(gmask, p, 1);
            q += __shfl_xor_sync(gmask, q, 1);
            float d0 = (rn - 2.f * p) + g_colnorm[c0];
            float d1 = (rn - 2.f * q) + g_colnorm[c1];
            unsigned long long k0 =
                ((unsigned long long)forder(d0) << 32) | (unsigned)c0;
            unsigned long long k1 =
                ((unsigned long long)forder(d1) << 32) | (unsigned)c1;
            if (k0 < best) best = k0;
            if (k1 < best) best = k1;
        }
        if (j < n) {
            int c0 = g_cand[gr][j];
            const float4* e0p = (const float4*)(CB + (size_t)c0 * DIM);
            float4 a0 = e0p[s * 2], a1 = e0p[s * 2 + 1];
            float p = x0.x * a0.x;
            p = fmaf(x0.y, a0.y, p); p = fmaf(x0.z, a0.z, p);
            p = fmaf(x0.w, a0.w, p); p = fmaf(x1.x, a1.x, p);
            p = fmaf(x1.y, a1.y, p); p = fmaf(x1.z, a1.z, p);
            p = fmaf(x1.w, a1.w, p);
            p += __shfl_xor_sync(gmask, p, 4);
            p += __shfl_xor_sync(gmask, p, 2);
            p += __shfl_xor_sync(gmask, p, 1);
            float d0 = (rn - 2.f * p) + g_colnorm[c0];
            unsigned long long k0 =
                ((unsigned long long)forder(d0) << 32) | (unsigned)c0;
            if (k0 < best) best = k0;
        }
    } else {
        // overflow fallback (rare): per-lane scan of all 512 codes
        for (int c = s; c < KCB; c += 8) {
            const float4* cp4 = (const float4*)(CB + (size_t)c * DIM);
            float d0 = 0.f, d1 = 0.f, d2 = 0.f, d3 = 0.f;
#pragma unroll
            for (int i = 0; i < DIM / 4; i++) {
                float4 x = xp4[i];
                float4 e = cp4[i];
                d0 = fmaf(x.x, e.x, d0);
                d1 = fmaf(x.y, e.y, d1);
                d2 = fmaf(x.z, e.z, d2);
                d3 = fmaf(x.w, e.w, d3);
            }
            float dot = (d0 + d1) + (d2 + d3);
            float d = (rn - 2.f * dot) + g_colnorm[c];
            unsigned long long key =
                ((unsigned long long)forder(d) << 32) | (unsigned)c;
            if (key < best) best = key;
        }
#pragma unroll
        for (int off = 4; off > 0; off >>= 1) {
            unsigned long long o = __shfl_xor_sync(gmask, best, off);
            if (o < best) best = o;
        }
    }
    int idx = (int)(best & 0xFFFFFFFFu);

    if (s == 0) {
        sidx[r] = idx;
        outI[gr] = (float)idx;
        atomicAdd(&g_count[idx], 1u);
    }

    // quantized: 8 threads x 8 floats (2 float4 each); outQ 16B-aligned
    {
        const float4* cp4 = (const float4*)(CB + (size_t)idx * DIM);
        float4* qp4 = (float4*)(outQ + (size_t)gr * DIM);
#pragma unroll
        for (int i = 0; i < 2; i++) {
            int j = s * 2 + i;
            float4 x = xp4[j];
            float4 e = cp4[j];
            float4 q;
            q.x = x.x + (e.x - x.x);
            q.y = x.y + (e.y - x.y);
            q.z = x.z + (e.z - x.z);
            q.w = x.w + (e.w - x.w);
            qp4[j] = q;
        }
    }

    // one-hot encodings: re-partition block as 8 warps x 4 rows, fully
    // coalesced 32-lane scalar stores (outE only 4B-aligned)
    __syncthreads();
    const int w = tid >> 5;
#pragma unroll
    for (int rr = 0; rr < 4; rr++) {
        int lr2 = w * 4 + rr;
        int idx2 = sidx[lr2];
        float* ep = outE + (size_t)(row0 + lr2) * KCB;
#pragma unroll
        for (int j = 0; j < 16; j++) {
            int col = j * 32 + lane;
            ep[col] = (col == idx2) ? 1.f : 0.f;
        }
    }
}

// ---------------------------------------------------------------------------
__global__ void perp_k(float* __restrict__ outP) {
    __shared__ float s[KCB];
    int t = threadIdx.x;
    float p = (float)g_count[t] / (float)N_ROWS;
    s[t] = p * logf(p + 1e-10f);
    __syncthreads();
    for (int o = KCB / 2; o > 0; o >>= 1) {
        if (t < o) s[t] += s[t + o];
        __syncthreads();
    }
    if (t == 0) outP[0] = expf(-s[0]);
}

// ---------------------------------------------------------------------------
extern "C" void kernel_launch(void* const* d_in, const int* in_sizes, int n_in,
                              void* d_out, int out_size) {
    const float* X = (const float*)d_in[0];
    const float* CB = (const float*)d_in[1];
    if (n_in >= 2 && in_sizes[0] == KCB * DIM) {
        X = (const float*)d_in[1];
        CB = (const float*)d_in[0];
    }
    float* out = (float*)d_out;
    float* outQ = out + OFF_Q;
    float* outP = out + OFF_P;
    float* outE = out + OFF_E;
    float* outI = out + OFF_I;
    float* outD = out + OFF_D;

    cudaFuncSetAttribute(gemm_k, cudaFuncAttributeMaxDynamicSharedMemorySize,
                         GEMM_SMEM_BYTES);

    rownorm_k<<<N_ROWS / 256, 256>>>(X);
    colnorm_k<<<2, 256>>>(CB);
    gemm_k<<<dim3(KCB / 128, N_ROWS / 64), 256, GEMM_SMEM_BYTES>>>(X, CB, outD);
    rescue_k<<<N_ROWS / RROWS, 256>>>(X, CB, outI, outQ, outE);
    perp_k<<<1, KCB>>>(outP);
}

// round 16
// speedup vs baseline: 1.4628x; 1.0926x over previous
#include <cuda_runtime.h>
#include <cuda_bf16.h>
#include <math.h>

#define N_ROWS 131072   // 32*64*64
#define DIM    64
#define KCB    512

// Output layout (concatenated, float32). Scalar perplexity misaligns
// everything after it to 4B -> scalar stores only into outE/outD.
#define OFF_Q 0
#define OFF_P (N_ROWS * DIM)
#define OFF_E (OFF_P + 1)
#define OFF_I (OFF_E + (size_t)N_ROWS * KCB)
#define OFF_D (OFF_I + N_ROWS)

#define CAND_CAP 16
#define CAND_MARGIN 1.2e-3f   // ~30x measured bf16 distance error (4e-5)

// Scratch
__device__ float g_rownorm[N_ROWS];
__device__ float g_colnorm[KCB];
__device__ unsigned int g_count[KCB];
__device__ int g_candn[N_ROWS];
__device__ unsigned short g_cand[N_ROWS][CAND_CAP];

// ---------------------------------------------------------------------------
__device__ __forceinline__ unsigned int forder(float f) {
    unsigned int u = __float_as_uint(f);
    unsigned int mask = ((int)u >> 31) | 0x80000000u;
    return u ^ mask;  // monotonic float -> uint
}

// pack two floats into bf16x2: lo half = first element (lower k), hi = second
__device__ __forceinline__ unsigned pack_bf16x2(float lo, float hi) {
    unsigned r;
    asm("cvt.rn.bf16x2.f32 %0, %1, %2;" : "=r"(r) : "f"(hi), "f"(lo));
    return r;
}

// m16n8k16 bf16 MMA, fp32 accumulate
__device__ __forceinline__ void mma16(float* c, unsigned a0, unsigned a1,
                                      unsigned a2, unsigned a3,
                                      unsigned b0, unsigned b1) {
    asm volatile(
        "mma.sync.aligned.m16n8k16.row.col.f32.bf16.bf16.f32 "
        "{%0,%1,%2,%3}, {%4,%5,%6,%7}, {%8,%9}, {%0,%1,%2,%3};"
        : "+f"(c[0]), "+f"(c[1]), "+f"(c[2]), "+f"(c[3])
        : "r"(a0), "r"(a1), "r"(a2), "r"(a3), "r"(b0), "r"(b1));
}

// ---------------------------------------------------------------------------
__global__ void rownorm_k(const float* __restrict__ X) {
    int r = blockIdx.x * blockDim.x + threadIdx.x;
    if (r >= N_ROWS) return;
    g_candn[r] = 0;
    const float4* p = (const float4*)(X + (size_t)r * DIM);
    float s = 0.f;
#pragma unroll
    for (int i = 0; i < DIM / 4; i++) {
        float4 v = p[i];
        s += v.x * v.x + v.y * v.y + v.z * v.z + v.w * v.w;
    }
    g_rownorm[r] = s;
}

__global__ void colnorm_k(const float* __restrict__ CB) {
    int r = blockIdx.x * blockDim.x + threadIdx.x;
    if (r >= KCB) return;
    g_count[r] = 0u;
    const float4* p = (const float4*)(CB + (size_t)r * DIM);
    float s = 0.f;
#pragma unroll
    for (int i = 0; i < DIM / 4; i++) {
        float4 v = p[i];
        s += v.x * v.x + v.y * v.y + v.z * v.z + v.w * v.w;
    }
    g_colnorm[r] = s;
}

// ---------------------------------------------------------------------------
// bf16 tensor-core distance GEMM (m16n8k16) + candidate collection.
// CTA 64x128, K=64 resident, 8 warps, 32x32/warp. k-PAIR permuted smem
// layout: within each 16-k block, pair p -> slot (p&3)*2 + (p>>2); thread t's
// fragment pairs {t, t+4} are one LDS.64 ({a0,a2}, {a1,a3}, {b0,b1}).
// 4 CTAs/SM (<=64 regs). Row-min via single REDUX (distances > 0 so raw
// float bits are order-preserving). Exact argmin via the fp32 rescue pass.
// ---------------------------------------------------------------------------
#define ROW_BYTES 160
#define AS_BYTES (64 * ROW_BYTES)      // 10240
#define CS_STRIDE 132
#define GEMM_SMEM_BYTES (64 * CS_STRIDE * 4)   // 33792 >= 30720 operand bytes

__global__ __launch_bounds__(256, 4) void gemm_k(const float* __restrict__ A,
                                                 const float* __restrict__ B,
                                                 float* __restrict__ outD) {
    extern __shared__ char smc[];
    char* As = smc;                 // [64 rows][160B] bf16, pair-permuted
    char* Bs = smc + AS_BYTES;      // [128 rows][160B] bf16(2*codebook)
    float* Cs = (float*)smc;        // [64][132] fp32, aliases post-MMA

    const int tid = threadIdx.x;
    const int lane = tid & 31;
    const int wid = tid >> 5;
    const int g = lane >> 2;
    const int t = lane & 3;
    const int wm0 = (wid & 1) * 32;      // 2 warp rows
    const int wn0 = (wid >> 1) * 32;     // 4 warp cols
    const int bm0 = blockIdx.y * 64;
    const int bk0 = blockIdx.x * 128;

    // Tile load: fp32 -> bf16 cvt + k-pair-permuted scatter.
    {
        const float4* Ag = (const float4*)(A + (size_t)bm0 * DIM);
        const float4* Bg = (const float4*)(B + (size_t)bk0 * DIM);
#pragma unroll
        for (int i = 0; i < 4; i++) {          // A: 64 rows = 1024 float4
            int t4 = tid + i * 256;
            int row = t4 >> 4;
            int c4 = (t4 & 15) * 4;
            int kblk = c4 >> 4;
            int p0 = (c4 & 15) >> 1;           // 0,2,4,6
            int s0 = ((p0 & 3) << 1) | (p0 >> 2);
            int s1 = (((p0 + 1) & 3) << 1) | ((p0 + 1) >> 2);
            char* rp = As + row * ROW_BYTES + kblk * 32;
            float4 va = Ag[t4];
            *(unsigned*)(rp + s0 * 4) = pack_bf16x2(va.x, va.y);
            *(unsigned*)(rp + s1 * 4) = pack_bf16x2(va.z, va.w);
        }
#pragma unroll
        for (int i = 0; i < 8; i++) {          // B: 128 rows = 2048 float4
            int t4 = tid + i * 256;
            int row = t4 >> 4;
            int c4 = (t4 & 15) * 4;
            int kblk = c4 >> 4;
            int p0 = (c4 & 15) >> 1;
            int s0 = ((p0 & 3) << 1) | (p0 >> 2);
            int s1 = (((p0 + 1) & 3) << 1) | ((p0 + 1) >> 2);
            char* rp = Bs + row * ROW_BYTES + kblk * 32;
            float4 vb = Bg[t4];
            *(unsigned*)(rp + s0 * 4) = pack_bf16x2(2.f * vb.x, 2.f * vb.y);
            *(unsigned*)(rp + s1 * 4) = pack_bf16x2(2.f * vb.z, 2.f * vb.w);
        }
    }
    __syncthreads();

    float acc[2][4][4];
#pragma unroll
    for (int mi = 0; mi < 2; mi++)
#pragma unroll
        for (int ni = 0; ni < 4; ni++)
#pragma unroll
            for (int j = 0; j < 4; j++) acc[mi][ni][j] = 0.f;

#pragma unroll
    for (int kt = 0; kt < 4; kt++) {           // 4 k-tiles of 16
        const int kb = kt * 32 + t * 8;
        uint2 fa[2][2];
#pragma unroll
        for (int mi = 0; mi < 2; mi++) {
            int r0 = wm0 + mi * 16 + g;
            fa[mi][0] = *(const uint2*)(As + r0 * ROW_BYTES + kb);        // {a0,a2}
            fa[mi][1] = *(const uint2*)(As + (r0 + 8) * ROW_BYTES + kb);  // {a1,a3}
        }
#pragma unroll
        for (int ni = 0; ni < 4; ni++) {       // fb live range = 2 regs
            int n = wn0 + ni * 8 + g;
            uint2 fb = *(const uint2*)(Bs + n * ROW_BYTES + kb);          // {b0,b1}
#pragma unroll
            for (int mi = 0; mi < 2; mi++)
                mma16(acc[mi][ni], fa[mi][0].x, fa[mi][1].x,
                      fa[mi][0].y, fa[mi][1].y, fb.x, fb.y);
        }
    }

    __syncthreads();
    // Stage accumulators via STS.64 (c0 even -> 8B aligned)
#pragma unroll
    for (int mi = 0; mi < 2; mi++)
#pragma unroll
        for (int ni = 0; ni < 4; ni++) {
            int r0 = wm0 + mi * 16 + g;
            int c0 = wn0 + ni * 8 + 2 * t;
            *(float2*)&Cs[r0 * CS_STRIDE + c0] =
                make_float2(acc[mi][ni][0], acc[mi][ni][1]);
            *(float2*)&Cs[(r0 + 8) * CS_STRIDE + c0] =
                make_float2(acc[mi][ni][2], acc[mi][ni][3]);
        }
    __syncthreads();

    // Distance stores + candidate collection. 8 warps x 8 rows = 64 rows.
    float cn4[4];
#pragma unroll
    for (int j = 0; j < 4; j++) cn4[j] = g_colnorm[bk0 + lane + 32 * j];

#pragma unroll 2
    for (int r = 0; r < 8; r++) {
        int lr = wid * 8 + r;
        int gr = bm0 + lr;
        float rn = g_rownorm[gr];
        const float* crow = &Cs[lr * CS_STRIDE];
        float* drow = outD + (size_t)gr * KCB + bk0;
        float v[4];
#pragma unroll
        for (int j = 0; j < 4; j++) {
            int c = lane + 32 * j;
            float d = (rn - crow[c]) + cn4[j];
            v[j] = d;
            drow[c] = d;
        }
        // row min via single REDUX: distances are positive -> raw float
        // bits are order-preserving as uints
        float mn = fminf(fminf(v[0], v[1]), fminf(v[2], v[3]));
        unsigned mnb = __reduce_min_sync(0xFFFFFFFFu, __float_as_uint(mn));
        float thr = __uint_as_float(mnb) + CAND_MARGIN;
#pragma unroll
        for (int j = 0; j < 4; j++) {
            if (v[j] <= thr) {
                int slot = atomicAdd(&g_candn[gr], 1);
                if (slot < CAND_CAP)
                    g_cand[gr][slot] = (unsigned short)(bk0 + lane + 32 * j);
            }
        }
    }
}

// ---------------------------------------------------------------------------
// rescue + outputs: block = 32 rows, 8 threads/row (warp = 4 rows).
// Phase order: (0) stage X, (1) stream one-hot ZEROS for the warp's 4 rows
// (stores drain while the latency-bound rescue runs), (2) exact-fp32
// candidate rescue, (3) __syncwarp, then poke the single 1.0 per row
// (same warp wrote that row's zeros -> warp-scope ordering suffices).
// ---------------------------------------------------------------------------
#define RROWS 32   // rows per block
__global__ __launch_bounds__(256, 4) void rescue_k(const float* __restrict__ X,
                                                   const float* __restrict__ CB,
                                                   float* __restrict__ outI,
                                                   float* __restrict__ outQ,
                                                   float* __restrict__ outE) {
    __shared__ float Xs[RROWS * DIM];           // 8 KB
    const int tid = threadIdx.x;
    const int r = tid >> 3;        // 0..31 row within block
    const int s = tid & 7;         // lane within row group
    const int lane = tid & 31;
    const int w = tid >> 5;
    const unsigned gmask = 0xFFu << (lane & 24);   // this 8-group's lanes
    const int row0 = blockIdx.x * RROWS;
    const int gr = row0 + r;

    // cooperative X stage: 32 rows x 64 floats = 512 float4
    {
        const float4* Xg = (const float4*)(X + (size_t)row0 * DIM);
        float4* Xs4 = (float4*)Xs;
#pragma unroll
        for (int i = 0; i < 2; i++) Xs4[tid + i * 256] = Xg[tid + i * 256];
    }
    __syncthreads();

    // Phase 1: stream one-hot ZEROS (warp w owns rows w*4..w*4+3);
    // fully-coalesced 32-lane scalar stores, issued before the rescue's
    // dependent loads so DRAM drains them in parallel.
#pragma unroll
    for (int rr = 0; rr < 4; rr++) {
        float* ep = outE + (size_t)(row0 + w * 4 + rr) * KCB;
#pragma unroll
        for (int j = 0; j < 16; j++) ep[j * 32 + lane] = 0.f;
    }

    // Phase 2: exact fp32 candidate rescue
    const float rn = g_rownorm[gr];
    const float4* xp4 = (const float4*)(Xs + r * DIM);
    const int n = g_candn[gr];

    unsigned long long best = 0xFFFFFFFFFFFFFFFFULL;
    if (n <= CAND_CAP) {
        float4 x0 = xp4[s * 2];
        float4 x1 = xp4[s * 2 + 1];
        int j = 0;
        for (; j + 1 < n; j += 2) {
            int c0 = g_cand[gr][j];
            int c1 = g_cand[gr][j + 1];
            const float4* e0p = (const float4*)(CB + (size_t)c0 * DIM);
            const float4* e1p = (const float4*)(CB + (size_t)c1 * DIM);
            float4 a0 = e0p[s * 2], a1 = e0p[s * 2 + 1];
            float4 b0 = e1p[s * 2], b1 = e1p[s * 2 + 1];
            float p = x0.x * a0.x;
            p = fmaf(x0.y, a0.y, p); p = fmaf(x0.z, a0.z, p);
            p = fmaf(x0.w, a0.w, p); p = fmaf(x1.x, a1.x, p);
            p = fmaf(x1.y, a1.y, p); p = fmaf(x1.z, a1.z, p);
            p = fmaf(x1.w, a1.w, p);
            float q = x0.x * b0.x;
            q = fmaf(x0.y, b0.y, q); q = fmaf(x0.z, b0.z, q);
            q = fmaf(x0.w, b0.w, q); q = fmaf(x1.x, b1.x, q);
            q = fmaf(x1.y, b1.y, q); q = fmaf(x1.z, b1.z, q);
            q = fmaf(x1.w, b1.w, q);
            p += __shfl_xor_sync(gmask, p, 4);
            q += __shfl_xor_sync(gmask, q, 4);
            p += __shfl_xor_sync(gmask, p, 2);
            q += __shfl_xor_sync(gmask, q, 2);
            p += __shfl_xor_sync(gmask, p, 1);
            q += __shfl_xor_sync(gmask, q, 1);
            float d0 = (rn - 2.f * p) + g_colnorm[c0];
            float d1 = (rn - 2.f * q) + g_colnorm[c1];
            unsigned long long k0 =
                ((unsigned long long)forder(d0) << 32) | (unsigned)c0;
            unsigned long long k1 =
                ((unsigned long long)forder(d1) << 32) | (unsigned)c1;
            if (k0 < best) best = k0;
            if (k1 < best) best = k1;
        }
        if (j < n) {
            int c0 = g_cand[gr][j];
            const float4* e0p = (const float4*)(CB + (size_t)c0 * DIM);
            float4 a0 = e0p[s * 2], a1 = e0p[s * 2 + 1];
            float p = x0.x * a0.x;
            p = fmaf(x0.y, a0.y, p); p = fmaf(x0.z, a0.z, p);
            p = fmaf(x0.w, a0.w, p); p = fmaf(x1.x, a1.x, p);
            p = fmaf(x1.y, a1.y, p); p = fmaf(x1.z, a1.z, p);
            p = fmaf(x1.w, a1.w, p);
            p += __shfl_xor_sync(gmask, p, 4);
            p += __shfl_xor_sync(gmask, p, 2);
            p += __shfl_xor_sync(gmask, p, 1);
            float d0 = (rn - 2.f * p) + g_colnorm[c0];
            unsigned long long k0 =
                ((unsigned long long)forder(d0) << 32) | (unsigned)c0;
            if (k0 < best) best = k0;
        }
    } else {
        // overflow fallback (rare): per-lane scan of all 512 codes
        for (int c = s; c < KCB; c += 8) {
            const float4* cp4 = (const float4*)(CB + (size_t)c * DIM);
            float d0 = 0.f, d1 = 0.f, d2 = 0.f, d3 = 0.f;
#pragma unroll
            for (int i = 0; i < DIM / 4; i++) {
                float4 x = xp4[i];
                float4 e = cp4[i];
                d0 = fmaf(x.x, e.x, d0);
                d1 = fmaf(x.y, e.y, d1);
                d2 = fmaf(x.z, e.z, d2);
                d3 = fmaf(x.w, e.w, d3);
            }
            float dot = (d0 + d1) + (d2 + d3);
            float d = (rn - 2.f * dot) + g_colnorm[c];
            unsigned long long key =
                ((unsigned long long)forder(d) << 32) | (unsigned)c;
            if (key < best) best = key;
        }
#pragma unroll
        for (int off = 4; off > 0; off >>= 1) {
            unsigned long long o = __shfl_xor_sync(gmask, best, off);
            if (o < best) best = o;
        }
    }
    int idx = (int)(best & 0xFFFFFFFFu);

    // quantized: 8 threads x 8 floats (2 float4 each); outQ 16B-aligned
    {
        const float4* cp4 = (const float4*)(CB + (size_t)idx * DIM);
        float4* qp4 = (float4*)(outQ + (size_t)gr * DIM);
#pragma unroll
        for (int i = 0; i < 2; i++) {
            int j = s * 2 + i;
            float4 x = xp4[j];
            float4 e = cp4[j];
            float4 q;
            q.x = x.x + (e.x - x.x);
            q.y = x.y + (e.y - x.y);
            q.z = x.z + (e.z - x.z);
            q.w = x.w + (e.w - x.w);
            qp4[j] = q;
        }
    }

    // Phase 3: order the 1.0 poke after this warp's zero stores
    __syncwarp();
    if (s == 0) {
        outI[gr] = (float)idx;
        atomicAdd(&g_count[idx], 1u);
        outE[(size_t)gr * KCB + idx] = 1.f;
    }
}

// ---------------------------------------------------------------------------
__global__ void perp_k(float* __restrict__ outP) {
    __shared__ float s[KCB];
    int t = threadIdx.x;
    float p = (float)g_count[t] / (float)N_ROWS;
    s[t] = p * logf(p + 1e-10f);
    __syncthreads();
    for (int o = KCB / 2; o > 0; o >>= 1) {
        if (t < o) s[t] += s[t + o];
        __syncthreads();
    }
    if (t == 0) outP[0] = expf(-s[0]);
}

// ---------------------------------------------------------------------------
extern "C" void kernel_launch(void* const* d_in, const int* in_sizes, int n_in,
                              void* d_out, int out_size) {
    const float* X = (const float*)d_in[0];
    const float* CB = (const float*)d_in[1];
    if (n_in >= 2 && in_sizes[0] == KCB * DIM) {
        X = (const float*)d_in[1];
        CB = (const float*)d_in[0];
    }
    float* out = (float*)d_out;
    float* outQ = out + OFF_Q;
    float* outP = out + OFF_P;
    float* outE = out + OFF_E;
    float* outI = out + OFF_I;
    float* outD = out + OFF_D;

    cudaFuncSetAttribute(gemm_k, cudaFuncAttributeMaxDynamicSharedMemorySize,
                         GEMM_SMEM_BYTES);

    rownorm_k<<<N_ROWS / 256, 256>>>(X);
    colnorm_k<<<2, 256>>>(CB);
    gemm_k<<<dim3(KCB / 128, N_ROWS / 64), 256, GEMM_SMEM_BYTES>>>(X, CB, outD);
    rescue_k<<<N_ROWS / RROWS, 256>>>(X, CB, outI, outQ, outE);
    perp_k<<<1, KCB>>>(outP);
}

// round 17
// speedup vs baseline: 1.5160x; 1.0364x over previous
#include <cuda_runtime.h>
#include <cuda_bf16.h>
#include <math.h>

#define N_ROWS 131072   // 32*64*64
#define DIM    64
#define KCB    512

// Output layout (concatenated, float32). Scalar perplexity misaligns
// everything after it to 4B -> scalar stores only into outE/outD.
#define OFF_Q 0
#define OFF_P (N_ROWS * DIM)
#define OFF_E (OFF_P + 1)
#define OFF_I (OFF_E + (size_t)N_ROWS * KCB)
#define OFF_D (OFF_I + N_ROWS)

#define CAND_CAP 16
#define CAND_MARGIN 1.2e-3f   // ~30x measured bf16 distance error (4e-5)

// Scratch
__device__ float g_rownorm[N_ROWS];
__device__ float g_colnorm[KCB];
__device__ unsigned int g_count[KCB];
__device__ int g_candn[N_ROWS];
__device__ unsigned short g_cand[N_ROWS][CAND_CAP];

// ---------------------------------------------------------------------------
__device__ __forceinline__ unsigned int forder(float f) {
    unsigned int u = __float_as_uint(f);
    unsigned int mask = ((int)u >> 31) | 0x80000000u;
    return u ^ mask;  // monotonic float -> uint
}

__device__ __forceinline__ void stcs(float* p, float v) {
    __stcs(p, v);   // streaming store: written once, never re-read
}

// pack two floats into bf16x2: lo half = first element (lower k), hi = second
__device__ __forceinline__ unsigned pack_bf16x2(float lo, float hi) {
    unsigned r;
    asm("cvt.rn.bf16x2.f32 %0, %1, %2;" : "=r"(r) : "f"(hi), "f"(lo));
    return r;
}

// m16n8k16 bf16 MMA, fp32 accumulate
__device__ __forceinline__ void mma16(float* c, unsigned a0, unsigned a1,
                                      unsigned a2, unsigned a3,
                                      unsigned b0, unsigned b1) {
    asm volatile(
        "mma.sync.aligned.m16n8k16.row.col.f32.bf16.bf16.f32 "
        "{%0,%1,%2,%3}, {%4,%5,%6,%7}, {%8,%9}, {%0,%1,%2,%3};"
        : "+f"(c[0]), "+f"(c[1]), "+f"(c[2]), "+f"(c[3])
        : "r"(a0), "r"(a1), "r"(a2), "r"(a3), "r"(b0), "r"(b1));
}

// ---------------------------------------------------------------------------
// norms: row norms ||x||^2 for all rows; first 512 threads also handle
// codebook norms + histogram reset (saves a launch).
__global__ void norms_k(const float* __restrict__ X, const float* __restrict__ CB) {
    int r = blockIdx.x * blockDim.x + threadIdx.x;
    if (r >= N_ROWS) return;
    g_candn[r] = 0;
    const float4* p = (const float4*)(X + (size_t)r * DIM);
    float s = 0.f;
#pragma unroll
    for (int i = 0; i < DIM / 4; i++) {
        float4 v = p[i];
        s += v.x * v.x + v.y * v.y + v.z * v.z + v.w * v.w;
    }
    g_rownorm[r] = s;
    if (r < KCB) {
        g_count[r] = 0u;
        const float4* q = (const float4*)(CB + (size_t)r * DIM);
        float sc = 0.f;
#pragma unroll
        for (int i = 0; i < DIM / 4; i++) {
            float4 v = q[i];
            sc += v.x * v.x + v.y * v.y + v.z * v.z + v.w * v.w;
        }
        g_colnorm[r] = sc;
    }
}

// ---------------------------------------------------------------------------
// bf16 tensor-core distance GEMM (m16n8k16) + candidate collection.
// CTA 64x128, K=64 resident, 8 warps, 32x32/warp. k-PAIR permuted smem
// layout: within each 16-k block, pair p -> slot (p&3)*2 + (p>>2); thread t's
// fragment pairs {t, t+4} are one LDS.64 ({a0,a2}, {a1,a3}, {b0,b1}).
// 4 CTAs/SM (<=64 regs). Row-min via single REDUX. Distances stored with
// .cs (streaming). Exact argmin via the fp32 rescue pass.
// ---------------------------------------------------------------------------
#define ROW_BYTES 160
#define AS_BYTES (64 * ROW_BYTES)      // 10240
#define CS_STRIDE 132
#define GEMM_SMEM_BYTES (64 * CS_STRIDE * 4)   // 33792 >= 30720 operand bytes

__global__ __launch_bounds__(256, 4) void gemm_k(const float* __restrict__ A,
                                                 const float* __restrict__ B,
                                                 float* __restrict__ outD) {
    extern __shared__ char smc[];
    char* As = smc;                 // [64 rows][160B] bf16, pair-permuted
    char* Bs = smc + AS_BYTES;      // [128 rows][160B] bf16(2*codebook)
    float* Cs = (float*)smc;        // [64][132] fp32, aliases post-MMA

    const int tid = threadIdx.x;
    const int lane = tid & 31;
    const int wid = tid >> 5;
    const int g = lane >> 2;
    const int t = lane & 3;
    const int wm0 = (wid & 1) * 32;      // 2 warp rows
    const int wn0 = (wid >> 1) * 32;     // 4 warp cols
    const int bm0 = blockIdx.y * 64;
    const int bk0 = blockIdx.x * 128;

    // Tile load: fp32 -> bf16 cvt + k-pair-permuted scatter.
    {
        const float4* Ag = (const float4*)(A + (size_t)bm0 * DIM);
        const float4* Bg = (const float4*)(B + (size_t)bk0 * DIM);
#pragma unroll
        for (int i = 0; i < 4; i++) {          // A: 64 rows = 1024 float4
            int t4 = tid + i * 256;
            int row = t4 >> 4;
            int c4 = (t4 & 15) * 4;
            int kblk = c4 >> 4;
            int p0 = (c4 & 15) >> 1;           // 0,2,4,6
            int s0 = ((p0 & 3) << 1) | (p0 >> 2);
            int s1 = (((p0 + 1) & 3) << 1) | ((p0 + 1) >> 2);
            char* rp = As + row * ROW_BYTES + kblk * 32;
            float4 va = Ag[t4];
            *(unsigned*)(rp + s0 * 4) = pack_bf16x2(va.x, va.y);
            *(unsigned*)(rp + s1 * 4) = pack_bf16x2(va.z, va.w);
        }
#pragma unroll
        for (int i = 0; i < 8; i++) {          // B: 128 rows = 2048 float4
            int t4 = tid + i * 256;
            int row = t4 >> 4;
            int c4 = (t4 & 15) * 4;
            int kblk = c4 >> 4;
            int p0 = (c4 & 15) >> 1;
            int s0 = ((p0 & 3) << 1) | (p0 >> 2);
            int s1 = (((p0 + 1) & 3) << 1) | ((p0 + 1) >> 2);
            char* rp = Bs + row * ROW_BYTES + kblk * 32;
            float4 vb = Bg[t4];
            *(unsigned*)(rp + s0 * 4) = pack_bf16x2(2.f * vb.x, 2.f * vb.y);
            *(unsigned*)(rp + s1 * 4) = pack_bf16x2(2.f * vb.z, 2.f * vb.w);
        }
    }
    __syncthreads();

    float acc[2][4][4];
#pragma unroll
    for (int mi = 0; mi < 2; mi++)
#pragma unroll
        for (int ni = 0; ni < 4; ni++)
#pragma unroll
            for (int j = 0; j < 4; j++) acc[mi][ni][j] = 0.f;

#pragma unroll
    for (int kt = 0; kt < 4; kt++) {           // 4 k-tiles of 16
        const int kb = kt * 32 + t * 8;
        uint2 fa[2][2];
#pragma unroll
        for (int mi = 0; mi < 2; mi++) {
            int r0 = wm0 + mi * 16 + g;
            fa[mi][0] = *(const uint2*)(As + r0 * ROW_BYTES + kb);        // {a0,a2}
            fa[mi][1] = *(const uint2*)(As + (r0 + 8) * ROW_BYTES + kb);  // {a1,a3}
        }
#pragma unroll
        for (int ni = 0; ni < 4; ni++) {       // fb live range = 2 regs
            int n = wn0 + ni * 8 + g;
            uint2 fb = *(const uint2*)(Bs + n * ROW_BYTES + kb);          // {b0,b1}
#pragma unroll
            for (int mi = 0; mi < 2; mi++)
                mma16(acc[mi][ni], fa[mi][0].x, fa[mi][1].x,
                      fa[mi][0].y, fa[mi][1].y, fb.x, fb.y);
        }
    }

    __syncthreads();
    // Stage accumulators via STS.64 (c0 even -> 8B aligned)
#pragma unroll
    for (int mi = 0; mi < 2; mi++)
#pragma unroll
        for (int ni = 0; ni < 4; ni++) {
            int r0 = wm0 + mi * 16 + g;
            int c0 = wn0 + ni * 8 + 2 * t;
            *(float2*)&Cs[r0 * CS_STRIDE + c0] =
                make_float2(acc[mi][ni][0], acc[mi][ni][1]);
            *(float2*)&Cs[(r0 + 8) * CS_STRIDE + c0] =
                make_float2(acc[mi][ni][2], acc[mi][ni][3]);
        }
    __syncthreads();

    // Distance stores (.cs streaming) + candidate collection.
    float cn4[4];
#pragma unroll
    for (int j = 0; j < 4; j++) cn4[j] = g_colnorm[bk0 + lane + 32 * j];

#pragma unroll 2
    for (int r = 0; r < 8; r++) {
        int lr = wid * 8 + r;
        int gr = bm0 + lr;
        float rn = g_rownorm[gr];
        const float* crow = &Cs[lr * CS_STRIDE];
        float* drow = outD + (size_t)gr * KCB + bk0;
        float v[4];
#pragma unroll
        for (int j = 0; j < 4; j++) {
            int c = lane + 32 * j;
            float d = (rn - crow[c]) + cn4[j];
            v[j] = d;
            stcs(&drow[c], d);
        }
        // row min via single REDUX: distances are positive -> raw float
        // bits are order-preserving as uints
        float mn = fminf(fminf(v[0], v[1]), fminf(v[2], v[3]));
        unsigned mnb = __reduce_min_sync(0xFFFFFFFFu, __float_as_uint(mn));
        float thr = __uint_as_float(mnb) + CAND_MARGIN;
#pragma unroll
        for (int j = 0; j < 4; j++) {
            if (v[j] <= thr) {
                int slot = atomicAdd(&g_candn[gr], 1);
                if (slot < CAND_CAP)
                    g_cand[gr][slot] = (unsigned short)(bk0 + lane + 32 * j);
            }
        }
    }
}

// ---------------------------------------------------------------------------
// rescue + outputs: block = 32 rows, 8 threads/row (warp = 4 rows).
// Phase order: (0) prefetch candidate count+list (registers) and stage X,
// (1) stream one-hot ZEROS (.cs) for the warp's 4 rows, (2) exact-fp32
// candidate rescue (candidate indices already register-resident),
// (3) __syncwarp, then poke the single 1.0 per row.
// ---------------------------------------------------------------------------
#define RROWS 32   // rows per block
__global__ __launch_bounds__(256, 4) void rescue_k(const float* __restrict__ X,
                                                   const float* __restrict__ CB,
                                                   float* __restrict__ outI,
                                                   float* __restrict__ outQ,
                                                   float* __restrict__ outE) {
    __shared__ float Xs[RROWS * DIM];           // 8 KB
    const int tid = threadIdx.x;
    const int r = tid >> 3;        // 0..31 row within block
    const int s = tid & 7;         // lane within row group
    const int lane = tid & 31;
    const int w = tid >> 5;
    const unsigned gmask = 0xFFu << (lane & 24);   // this 8-group's lanes
    const int row0 = blockIdx.x * RROWS;
    const int gr = row0 + r;

    // Phase 0a: prefetch candidate count + packed candidate list (2x uint4)
    const int n = g_candn[gr];
    uint4 cl0 = *(const uint4*)&g_cand[gr][0];   // cands 0..7 (u16 packed)
    uint4 cl1 = *(const uint4*)&g_cand[gr][8];   // cands 8..15
    unsigned short cl[CAND_CAP];
    *(uint4*)&cl[0] = cl0;
    *(uint4*)&cl[8] = cl1;

    // Phase 0b: cooperative X stage: 32 rows x 64 floats = 512 float4
    {
        const float4* Xg = (const float4*)(X + (size_t)row0 * DIM);
        float4* Xs4 = (float4*)Xs;
#pragma unroll
        for (int i = 0; i < 2; i++) Xs4[tid + i * 256] = Xg[tid + i * 256];
    }
    __syncthreads();

    // Phase 1: stream one-hot ZEROS (warp w owns rows w*4..w*4+3);
    // fully-coalesced .cs stores drain while the rescue runs.
#pragma unroll
    for (int rr = 0; rr < 4; rr++) {
        float* ep = outE + (size_t)(row0 + w * 4 + rr) * KCB;
#pragma unroll
        for (int j = 0; j < 16; j++) stcs(&ep[j * 32 + lane], 0.f);
    }

    // Phase 2: exact fp32 candidate rescue
    const float rn = g_rownorm[gr];
    const float4* xp4 = (const float4*)(Xs + r * DIM);

    unsigned long long best = 0xFFFFFFFFFFFFFFFFULL;
    if (n <= CAND_CAP) {
        float4 x0 = xp4[s * 2];
        float4 x1 = xp4[s * 2 + 1];
        int j = 0;
        for (; j + 1 < n; j += 2) {
            int c0 = cl[j];
            int c1 = cl[j + 1];
            const float4* e0p = (const float4*)(CB + (size_t)c0 * DIM);
            const float4* e1p = (const float4*)(CB + (size_t)c1 * DIM);
            float4 a0 = e0p[s * 2], a1 = e0p[s * 2 + 1];
            float4 b0 = e1p[s * 2], b1 = e1p[s * 2 + 1];
            float p = x0.x * a0.x;
            p = fmaf(x0.y, a0.y, p); p = fmaf(x0.z, a0.z, p);
            p = fmaf(x0.w, a0.w, p); p = fmaf(x1.x, a1.x, p);
            p = fmaf(x1.y, a1.y, p); p = fmaf(x1.z, a1.z, p);
            p = fmaf(x1.w, a1.w, p);
            float q = x0.x * b0.x;
            q = fmaf(x0.y, b0.y, q); q = fmaf(x0.z, b0.z, q);
            q = fmaf(x0.w, b0.w, q); q = fmaf(x1.x, b1.x, q);
            q = fmaf(x1.y, b1.y, q); q = fmaf(x1.z, b1.z, q);
            q = fmaf(x1.w, b1.w, q);
            p += __shfl_xor_sync(gmask, p, 4);
            q += __shfl_xor_sync(gmask, q, 4);
            p += __shfl_xor_sync(gmask, p, 2);
            q += __shfl_xor_sync(gmask, q, 2);
            p += __shfl_xor_sync(gmask, p, 1);
            q += __shfl_xor_sync(gmask, q, 1);
            float d0 = (rn - 2.f * p) + g_colnorm[c0];
            float d1 = (rn - 2.f * q) + g_colnorm[c1];
            unsigned long long k0 =
                ((unsigned long long)forder(d0) << 32) | (unsigned)c0;
            unsigned long long k1 =
                ((unsigned long long)forder(d1) << 32) | (unsigned)c1;
            if (k0 < best) best = k0;
            if (k1 < best) best = k1;
        }
        if (j < n) {
            int c0 = cl[j];
            const float4* e0p = (const float4*)(CB + (size_t)c0 * DIM);
            float4 a0 = e0p[s * 2], a1 = e0p[s * 2 + 1];
            float p = x0.x * a0.x;
            p = fmaf(x0.y, a0.y, p); p = fmaf(x0.z, a0.z, p);
            p = fmaf(x0.w, a0.w, p); p = fmaf(x1.x, a1.x, p);
            p = fmaf(x1.y, a1.y, p); p = fmaf(x1.z, a1.z, p);
            p = fmaf(x1.w, a1.w, p);
            p += __shfl_xor_sync(gmask, p, 4);
            p += __shfl_xor_sync(gmask, p, 2);
            p += __shfl_xor_sync(gmask, p, 1);
            float d0 = (rn - 2.f * p) + g_colnorm[c0];
            unsigned long long k0 =
                ((unsigned long long)forder(d0) << 32) | (unsigned)c0;
            if (k0 < best) best = k0;
        }
    } else {
        // overflow fallback (rare): per-lane scan of all 512 codes
        for (int c = s; c < KCB; c += 8) {
            const float4* cp4 = (const float4*)(CB + (size_t)c * DIM);
            float d0 = 0.f, d1 = 0.f, d2 = 0.f, d3 = 0.f;
#pragma unroll
            for (int i = 0; i < DIM / 4; i++) {
                float4 x = xp4[i];
                float4 e = cp4[i];
                d0 = fmaf(x.x, e.x, d0);
                d1 = fmaf(x.y, e.y, d1);
                d2 = fmaf(x.z, e.z, d2);
                d3 = fmaf(x.w, e.w, d3);
            }
            float dot = (d0 + d1) + (d2 + d3);
            float d = (rn - 2.f * dot) + g_colnorm[c];
            unsigned long long key =
                ((unsigned long long)forder(d) << 32) | (unsigned)c;
            if (key < best) best = key;
        }
#pragma unroll
        for (int off = 4; off > 0; off >>= 1) {
            unsigned long long o = __shfl_xor_sync(gmask, best, off);
            if (o < best) best = o;
        }
    }
    int idx = (int)(best & 0xFFFFFFFFu);

    // quantized: 8 threads x 8 floats (2 float4 each); outQ 16B-aligned
    {
        const float4* cp4 = (const float4*)(CB + (size_t)idx * DIM);
        float4* qp4 = (float4*)(outQ + (size_t)gr * DIM);
#pragma unroll
        for (int i = 0; i < 2; i++) {
            int j = s * 2 + i;
            float4 x = xp4[j];
            float4 e = cp4[j];
            float4 q;
            q.x = x.x + (e.x - x.x);
            q.y = x.y + (e.y - x.y);
            q.z = x.z + (e.z - x.z);
            q.w = x.w + (e.w - x.w);
            qp4[j] = q;
        }
    }

    // Phase 3: order the 1.0 poke after this warp's zero stores
    __syncwarp();
    if (s == 0) {
        outI[gr] = (float)idx;
        atomicAdd(&g_count[idx], 1u);
        outE[(size_t)gr * KCB + idx] = 1.f;
    }
}

// ---------------------------------------------------------------------------
__global__ void perp_k(float* __restrict__ outP) {
    __shared__ float s[KCB];
    int t = threadIdx.x;
    float p = (float)g_count[t] / (float)N_ROWS;
    s[t] = p * logf(p + 1e-10f);
    __syncthreads();
    for (int o = KCB / 2; o > 0; o >>= 1) {
        if (t < o) s[t] += s[t + o];
        __syncthreads();
    }
    if (t == 0) outP[0] = expf(-s[0]);
}

// ---------------------------------------------------------------------------
extern "C" void kernel_launch(void* const* d_in, const int* in_sizes, int n_in,
                              void* d_out, int out_size) {
    const float* X = (const float*)d_in[0];
    const float* CB = (const float*)d_in[1];
    if (n_in >= 2 && in_sizes[0] == KCB * DIM) {
        X = (const float*)d_in[1];
        CB = (const float*)d_in[0];
    }
    float* out = (float*)d_out;
    float* outQ = out + OFF_Q;
    float* outP = out + OFF_P;
    float* outE = out + OFF_E;
    float* outI = out + OFF_I;
    float* outD = out + OFF_D;

    cudaFuncSetAttribute(gemm_k, cudaFuncAttributeMaxDynamicSharedMemorySize,
                         GEMM_SMEM_BYTES);

    norms_k<<<N_ROWS / 256, 256>>>(X, CB);
    gemm_k<<<dim3(KCB / 128, N_ROWS / 64), 256, GEMM_SMEM_BYTES>>>(X, CB, outD);
    rescue_k<<<N_ROWS / RROWS, 256>>>(X, CB, outI, outQ, outE);
    perp_k<<<1, KCB>>>(outP);
}